// round 6
// baseline (speedup 1.0000x reference)
#include <cuda_runtime.h>
#include <cuda_bf16.h>
#include <math.h>
#include <cstdint>

// Problem dims
#define MROWS 16384   // B*T = 4*4096
#define DDIM  1024
#define TLEN  4096
#define CHUNKS 32
#define CHLEN  (TLEN / CHUNKS)   // 128
#define NCHAIN 4096              // B * D

// ---------------- scratch (device globals; no allocation allowed) ----------
__device__ float g_lin[MROWS * DDIM];
__device__ float g_rg [MROWS * DDIM];
__device__ float g_rt [MROWS * DDIM];
__device__ float g_it [MROWS * DDIM];
__device__ float g_res[MROWS * DDIM];
__device__ float g_hl [MROWS * DDIM];
__device__ __nv_bfloat16 g_A0h[MROWS * DDIM];
__device__ __nv_bfloat16 g_A0l[MROWS * DDIM];
__device__ __nv_bfloat16 g_A1h[MROWS * DDIM];
__device__ __nv_bfloat16 g_A1l[MROWS * DDIM];
__device__ __nv_bfloat16 g_Wh[DDIM * DDIM];
__device__ __nv_bfloat16 g_Wl[DDIM * DDIM];
__device__ float g_Acar[NCHAIN * CHUNKS];
__device__ float g_Hcar[NCHAIN * CHUNKS];
__device__ float g_carry[NCHAIN * CHUNKS];

// ---------------- base-ISA tensor helpers ----------------------------------
__device__ __forceinline__ uint32_t smem_to_u32(const void* p) {
    uint32_t a;
    asm("{ .reg .u64 t; cvta.to.shared.u64 t, %1; cvt.u32.u64 %0, t; }"
        : "=r"(a) : "l"(p));
    return a;
}
__device__ __forceinline__ void cpasync16(uint32_t dst, const void* src) {
    asm volatile("cp.async.cg.shared.global [%0], [%1], 16;"
                 :: "r"(dst), "l"(src) : "memory");
}
#define CP_COMMIT() asm volatile("cp.async.commit_group;" ::: "memory")
#define CP_WAIT(n)  asm volatile("cp.async.wait_group %0;" :: "n"(n) : "memory")

__device__ __forceinline__ void ldsm4(uint32_t addr, uint32_t* r) {
    asm volatile("ldmatrix.sync.aligned.m8n8.x4.shared.b16 {%0,%1,%2,%3}, [%4];"
                 : "=r"(r[0]), "=r"(r[1]), "=r"(r[2]), "=r"(r[3]) : "r"(addr));
}
__device__ __forceinline__ void mma16816(float* c, const uint32_t* a, const uint32_t* b) {
    asm volatile(
        "mma.sync.aligned.m16n8k16.row.col.f32.bf16.bf16.f32 "
        "{%0,%1,%2,%3}, {%4,%5,%6,%7}, {%8,%9}, {%0,%1,%2,%3};"
        : "+f"(c[0]), "+f"(c[1]), "+f"(c[2]), "+f"(c[3])
        : "r"(a[0]), "r"(a[1]), "r"(a[2]), "r"(a[3]), "r"(b[0]), "r"(b[1]));
}

// ---------------- math helpers ---------------------------------------------
__device__ __forceinline__ float gelu_exact(float x) {
    return 0.5f * x * (1.0f + erff(x * 0.70710678118654752440f));
}
__device__ __forceinline__ float sigmoidf_(float x) {
    return 1.0f / (1.0f + expf(-x));
}
__device__ __forceinline__ void split2(float a, float b,
                                       __nv_bfloat162& h, __nv_bfloat162& l) {
    h = __floats2bfloat162_rn(a, b);
    l = __floats2bfloat162_rn(a - __low2float(h), b - __high2float(h));
}

// ---------------- fp32 -> (hi, lo) bf16 split (weights) --------------------
__global__ void split_kernel(const float* __restrict__ src,
                             __nv_bfloat16* __restrict__ hi,
                             __nv_bfloat16* __restrict__ lo, int n4) {
    int i = blockIdx.x * 256 + threadIdx.x;
    if (i >= n4) return;
    float4 v = ((const float4*)src)[i];
    __nv_bfloat162 h01, l01, h23, l23;
    split2(v.x, v.y, h01, l01);
    split2(v.z, v.w, h23, l23);
    ((__nv_bfloat162*)hi)[2 * i]     = h01;
    ((__nv_bfloat162*)hi)[2 * i + 1] = h23;
    ((__nv_bfloat162*)lo)[2 * i]     = l01;
    ((__nv_bfloat162*)lo)[2 * i + 1] = l23;
}

// ---------------- split-bf16 mma.sync GEMM ---------------------------------
// C[M,N] = (Ah+Al)[M,K] @ (Bh+Bl)[N,K]^T + bias (+ add), fp32 accumulate.
// CTA tile 128x128, K-chunk 64, 3-stage cp.async pipeline, 512 threads,
// warp grid 4x4 (warp tile 32x32), 1 CTA/SM.
#define TILE_BYTES  16384            // 128 x 64 bf16
#define STAGE_BYTES 65536            // 4 tiles: Ah, Al, Bh, Bl
#define NSTAGE 3
#define NCHUNK (DDIM / 64)           // 16

__device__ __forceinline__ uint32_t swaddr(uint32_t tile, uint32_t row, uint32_t kb) {
    uint32_t off = row * 128u + kb;
    return tile + (off ^ ((off >> 3) & 0x70u));
}

__global__ void __launch_bounds__(512, 1)
mma_gemm_kernel(const __nv_bfloat16* __restrict__ Ah, const __nv_bfloat16* __restrict__ Al,
                const __nv_bfloat16* __restrict__ Bh, const __nv_bfloat16* __restrict__ Bl,
                const float* __restrict__ bias, const float* __restrict__ addp,
                float* __restrict__ C, int doAdd,
                __nv_bfloat16* __restrict__ Sh, __nv_bfloat16* __restrict__ Sl) {
    extern __shared__ __align__(1024) char smem_raw[];
    uint32_t smem0 = smem_to_u32(smem_raw);
    uint32_t tbase = (smem0 + 1023u) & ~1023u;

    int tid = threadIdx.x;
    int wid = tid >> 5;
    int lane = tid & 31;
    int m0 = blockIdx.y * 128;
    int n0 = blockIdx.x * 128;

    // ---- producer mapping: 8 x 16B vecs per thread per stage ----
    // i = 0..7: tile = i>>1 (Ah,Al,Bh,Bl), row = (tid>>3) + 64*(i&1), col16 = tid&7
    int row_base = tid >> 3;        // 0..63
    int col = tid & 7;
    const char* srcb[8];
    uint32_t stsoff[8];
    {
        const char* base4[4];
        base4[0] = (const char*)(Ah + (size_t)m0 * DDIM);
        base4[1] = (const char*)(Al + (size_t)m0 * DDIM);
        base4[2] = (const char*)(Bh + (size_t)n0 * DDIM);
        base4[3] = (const char*)(Bl + (size_t)n0 * DDIM);
        #pragma unroll
        for (int i = 0; i < 8; i++) {
            uint32_t rr = (uint32_t)row_base + 64u * (i & 1);
            srcb[i] = base4[i >> 1] + (size_t)rr * 2048 + col * 16;
            uint32_t off = rr * 128u + (uint32_t)col * 16u;
            stsoff[i] = (uint32_t)(i >> 1) * TILE_BYTES + (off ^ ((off >> 3) & 0x70u));
        }
    }

    #define ISSUE_STAGE(buf, chunk) do { \
        uint32_t db_ = tbase + (uint32_t)(buf) * STAGE_BYTES; \
        _Pragma("unroll") \
        for (int i_ = 0; i_ < 8; i_++) \
            cpasync16(db_ + stsoff[i_], srcb[i_] + (size_t)(chunk) * 128); \
        CP_COMMIT(); \
    } while (0)

    // ---- consumer mapping: 16 warps, warp grid 4 M x 4 N, tile 32x32 ----
    int warp_m = wid & 3;
    int warp_n = wid >> 2;
    uint32_t ar  = (uint32_t)((lane & 7) + ((lane >> 3) & 1) * 8);
    uint32_t akb = (uint32_t)(((lane >> 4) & 1) * 16);
    uint32_t br  = (uint32_t)((lane & 7) + ((lane >> 4) & 1) * 8);
    uint32_t bkb = (uint32_t)(((lane >> 3) & 1) * 16);

    float acc[2][4][4];
    #pragma unroll
    for (int i = 0; i < 2; i++)
        #pragma unroll
        for (int j = 0; j < 4; j++)
            #pragma unroll
            for (int q = 0; q < 4; q++) acc[i][j][q] = 0.0f;

    ISSUE_STAGE(0, 0);
    ISSUE_STAGE(1, 1);

    for (int c = 0; c < NCHUNK; c++) {
        if (c < NCHUNK - 1) { CP_WAIT(1); } else { CP_WAIT(0); }
        __syncthreads();
        if (c + 2 < NCHUNK) ISSUE_STAGE((c + 2) % NSTAGE, c + 2);

        uint32_t sb = tbase + (uint32_t)(c % NSTAGE) * STAGE_BYTES;
        uint32_t tAh = sb;
        uint32_t tAl = sb + TILE_BYTES;
        uint32_t tBh = sb + 2 * TILE_BYTES;
        uint32_t tBl = sb + 3 * TILE_BYTES;

        #pragma unroll
        for (int k16 = 0; k16 < 4; k16++) {
            uint32_t kb = (uint32_t)k16 * 32u;
            uint32_t ah[2][4], al[2][4], bh[2][4], bl[2][4];
            #pragma unroll
            for (int mt = 0; mt < 2; mt++)
                ldsm4(swaddr(tAh, (uint32_t)(warp_m * 32 + mt * 16) + ar, kb + akb), ah[mt]);
            #pragma unroll
            for (int p = 0; p < 2; p++)
                ldsm4(swaddr(tBh, (uint32_t)(warp_n * 32 + p * 16) + br, kb + bkb), bh[p]);
            // term 1: Ah @ Bh
            #pragma unroll
            for (int mt = 0; mt < 2; mt++)
                #pragma unroll
                for (int p = 0; p < 2; p++) {
                    mma16816(acc[mt][2 * p],     ah[mt], &bh[p][0]);
                    mma16816(acc[mt][2 * p + 1], ah[mt], &bh[p][2]);
                }
            // term 2: Ah @ Bl
            #pragma unroll
            for (int p = 0; p < 2; p++)
                ldsm4(swaddr(tBl, (uint32_t)(warp_n * 32 + p * 16) + br, kb + bkb), bl[p]);
            #pragma unroll
            for (int mt = 0; mt < 2; mt++)
                #pragma unroll
                for (int p = 0; p < 2; p++) {
                    mma16816(acc[mt][2 * p],     ah[mt], &bl[p][0]);
                    mma16816(acc[mt][2 * p + 1], ah[mt], &bl[p][2]);
                }
            // term 3: Al @ Bh
            #pragma unroll
            for (int mt = 0; mt < 2; mt++)
                ldsm4(swaddr(tAl, (uint32_t)(warp_m * 32 + mt * 16) + ar, kb + akb), al[mt]);
            #pragma unroll
            for (int mt = 0; mt < 2; mt++)
                #pragma unroll
                for (int p = 0; p < 2; p++) {
                    mma16816(acc[mt][2 * p],     al[mt], &bh[p][0]);
                    mma16816(acc[mt][2 * p + 1], al[mt], &bh[p][2]);
                }
        }
    }

    // ---- epilogue ----
    int lm = lane >> 2;
    int lc = (lane & 3) * 2;
    int cm = m0 + warp_m * 32;
    int cn = n0 + warp_n * 32;
    #pragma unroll
    for (int mt = 0; mt < 2; mt++) {
        #pragma unroll
        for (int nt = 0; nt < 4; nt++) {
            int r0 = cm + mt * 16 + lm;
            int cc = cn + nt * 8 + lc;
            float2 bv = *(const float2*)&bias[cc];
            float* a = acc[mt][nt];
            float2 o0 = make_float2(a[0] + bv.x, a[1] + bv.y);
            float2 o1 = make_float2(a[2] + bv.x, a[3] + bv.y);
            size_t off0 = (size_t)r0 * DDIM + cc;
            size_t off1 = (size_t)(r0 + 8) * DDIM + cc;
            if (doAdd) {
                float2 q0 = *(const float2*)(addp + off0);
                float2 q1 = *(const float2*)(addp + off1);
                o0.x += q0.x; o0.y += q0.y;
                o1.x += q1.x; o1.y += q1.y;
            }
            *(float2*)(C + off0) = o0;
            *(float2*)(C + off1) = o1;
            if (Sh) {
                __nv_bfloat162 h0, l0, h1, l1;
                split2(o0.x, o0.y, h0, l0);
                split2(o1.x, o1.y, h1, l1);
                *(__nv_bfloat162*)(Sh + off0) = h0;
                *(__nv_bfloat162*)(Sl + off0) = l0;
                *(__nv_bfloat162*)(Sh + off1) = h1;
                *(__nv_bfloat162*)(Sl + off1) = l1;
            }
        }
    }
}

// ---------------- rmsnorm -> bf16 split ------------------------------------
__global__ void rmsnorm_split_kernel(const float* __restrict__ x,
                                     const float* __restrict__ gw,
                                     __nv_bfloat16* __restrict__ Sh,
                                     __nv_bfloat16* __restrict__ Sl) {
    int row = blockIdx.x;
    const float4* xr = (const float4*)(x + (size_t)row * DDIM);
    float4 v = xr[threadIdx.x];
    float ss = v.x * v.x + v.y * v.y + v.z * v.z + v.w * v.w;
    #pragma unroll
    for (int o = 16; o > 0; o >>= 1) ss += __shfl_xor_sync(0xffffffffu, ss, o);
    __shared__ float sred[8];
    if ((threadIdx.x & 31) == 0) sred[threadIdx.x >> 5] = ss;
    __syncthreads();
    float total = 0.0f;
    #pragma unroll
    for (int i = 0; i < 8; i++) total += sred[i];
    float n = fmaxf(sqrtf(total), 1e-12f);
    float s = 32.0f / n;
    float4 g = ((const float4*)gw)[threadIdx.x];
    float o0 = v.x * s * g.x, o1 = v.y * s * g.y;
    float o2 = v.z * s * g.z, o3 = v.w * s * g.w;
    __nv_bfloat162 h01, l01, h23, l23;
    split2(o0, o1, h01, l01);
    split2(o2, o3, h23, l23);
    size_t base2 = (size_t)row * (DDIM / 2) + threadIdx.x * 2;
    ((__nv_bfloat162*)Sh)[base2]     = h01;
    ((__nv_bfloat162*)Sh)[base2 + 1] = h23;
    ((__nv_bfloat162*)Sl)[base2]     = l01;
    ((__nv_bfloat162*)Sl)[base2 + 1] = l23;
}

// ---------------- chunked RG-LRU scan --------------------------------------
__global__ void scan1_kernel(const float* __restrict__ rt, const float* __restrict__ it,
                             const float* __restrict__ rg, const float* __restrict__ Lam,
                             float* __restrict__ hl,
                             float* __restrict__ Acar, float* __restrict__ Hcar) {
    int i = blockIdx.x * 256 + threadIdx.x;     // 0 .. 131071
    int chain = i & (NCHAIN - 1);
    int chunk = i >> 12;
    int b = chain >> 10, d = chain & (DDIM - 1);
    size_t base = ((size_t)b * TLEN + (size_t)chunk * CHLEN) * DDIM + d;
    float la = -log1pf(expf(-Lam[d]));
    float h = 0.0f, P = 1.0f;
    for (int t = 0; t < CHLEN; t++) {
        size_t a_ = base + (size_t)t * DDIM;
        float r  = rt[a_];
        float iv = it[a_];
        float xv = rg[a_];
        float a = expf(la * sigmoidf_(r) * 0.125f);
        float g = sqrtf(fmaxf(1.0f - a * a, 0.0f)) * sigmoidf_(iv) * xv;
        h = fmaf(a, h, g);
        P *= a;
        hl[a_] = h;
    }
    Acar[i] = P;
    Hcar[i] = h;
}

__global__ void scan2_kernel(const float* __restrict__ Acar, const float* __restrict__ Hcar,
                             float* __restrict__ carry) {
    int chain = blockIdx.x * 256 + threadIdx.x;   // 0..4095
    float h = 0.0f;
    #pragma unroll
    for (int c = 0; c < CHUNKS; c++) {
        int idx = c * NCHAIN + chain;
        carry[idx] = h;
        h = fmaf(Acar[idx], h, Hcar[idx]);
    }
}

__global__ void scan3_kernel(const float* __restrict__ rt, const float* __restrict__ hl,
                             const float* __restrict__ carry, const float* __restrict__ lin,
                             const float* __restrict__ Lam,
                             __nv_bfloat16* __restrict__ Sh, __nv_bfloat16* __restrict__ Sl) {
    int i = blockIdx.x * 256 + threadIdx.x;
    int chain = i & (NCHAIN - 1);
    int chunk = i >> 12;
    int b = chain >> 10, d = chain & (DDIM - 1);
    size_t base = ((size_t)b * TLEN + (size_t)chunk * CHLEN) * DDIM + d;
    float la = -log1pf(expf(-Lam[d]));
    float cin = carry[i];
    float P = 1.0f;
    for (int t = 0; t < CHLEN; t++) {
        size_t a_ = base + (size_t)t * DDIM;
        float r = rt[a_];
        float a = expf(la * sigmoidf_(r) * 0.125f);
        P *= a;
        float h = fmaf(P, cin, hl[a_]);
        float l = lin[a_];
        float o = gelu_exact(l) * h;
        __nv_bfloat16 bh = __float2bfloat16_rn(o);
        __nv_bfloat16 bl = __float2bfloat16_rn(o - __bfloat162float(bh));
        Sh[a_] = bh;
        Sl[a_] = bl;
    }
}

// ---------------- gelu(sigmoid(t1)) * t2 -> bf16 split ---------------------
__global__ void comb_split_kernel(const float* __restrict__ t1,
                                  const float* __restrict__ t2,
                                  __nv_bfloat16* __restrict__ Sh,
                                  __nv_bfloat16* __restrict__ Sl) {
    int i = blockIdx.x * blockDim.x + threadIdx.x;
    if (i >= MROWS * DDIM / 4) return;
    float4 a = ((const float4*)t1)[i];
    float4 b = ((const float4*)t2)[i];
    float o0 = gelu_exact(sigmoidf_(a.x)) * b.x;
    float o1 = gelu_exact(sigmoidf_(a.y)) * b.y;
    float o2 = gelu_exact(sigmoidf_(a.z)) * b.z;
    float o3 = gelu_exact(sigmoidf_(a.w)) * b.w;
    __nv_bfloat162 h01, l01, h23, l23;
    split2(o0, o1, h01, l01);
    split2(o2, o3, h23, l23);
    ((__nv_bfloat162*)Sh)[2 * i]     = h01;
    ((__nv_bfloat162*)Sh)[2 * i + 1] = h23;
    ((__nv_bfloat162*)Sl)[2 * i]     = l01;
    ((__nv_bfloat162*)Sl)[2 * i + 1] = l23;
}

// ---------------- launch ---------------------------------------------------
extern "C" void kernel_launch(void* const* d_in, const int* in_sizes, int n_in,
                              void* d_out, int out_size) {
    const float* x      = (const float*)d_in[0];
    const float* g1     = (const float*)d_in[1];
    const float* g2     = (const float*)d_in[2];
    const float* W_lin  = (const float*)d_in[3];
    const float* b_lin  = (const float*)d_in[4];
    const float* W_conv = (const float*)d_in[5];
    const float* b_conv = (const float*)d_in[6];
    const float* W_lin2 = (const float*)d_in[7];
    const float* b_lin2 = (const float*)d_in[8];
    const float* Wa     = (const float*)d_in[9];
    const float* ba     = (const float*)d_in[10];
    const float* Wx     = (const float*)d_in[11];
    const float* bx     = (const float*)d_in[12];
    const float* Lam    = (const float*)d_in[13];
    const float* W1     = (const float*)d_in[14];
    const float* b1     = (const float*)d_in[15];
    const float* W2     = (const float*)d_in[16];
    const float* b2     = (const float*)d_in[17];
    const float* W3     = (const float*)d_in[18];
    const float* b3     = (const float*)d_in[19];
    float* out = (float*)d_out;

    float *lin, *rg, *rt, *it, *res, *hl, *Acar, *Hcar, *carry;
    __nv_bfloat16 *A0h, *A0l, *A1h, *A1l, *Wh, *Wl;
    cudaGetSymbolAddress((void**)&lin, g_lin);
    cudaGetSymbolAddress((void**)&rg,  g_rg);
    cudaGetSymbolAddress((void**)&rt,  g_rt);
    cudaGetSymbolAddress((void**)&it,  g_it);
    cudaGetSymbolAddress((void**)&res, g_res);
    cudaGetSymbolAddress((void**)&hl,  g_hl);
    cudaGetSymbolAddress((void**)&Acar, g_Acar);
    cudaGetSymbolAddress((void**)&Hcar, g_Hcar);
    cudaGetSymbolAddress((void**)&carry, g_carry);
    cudaGetSymbolAddress((void**)&A0h, g_A0h);
    cudaGetSymbolAddress((void**)&A0l, g_A0l);
    cudaGetSymbolAddress((void**)&A1h, g_A1h);
    cudaGetSymbolAddress((void**)&A1l, g_A1l);
    cudaGetSymbolAddress((void**)&Wh,  g_Wh);
    cudaGetSymbolAddress((void**)&Wl,  g_Wl);

    const int GEMM_SMEM = NSTAGE * STAGE_BYTES + 1024;   // 197632
    cudaFuncSetAttribute(mma_gemm_kernel,
                         cudaFuncAttributeMaxDynamicSharedMemorySize, GEMM_SMEM);

    dim3 gg(DDIM / 128, MROWS / 128);   // (8, 128)
    int ewBlocks  = (MROWS * DDIM / 4 + 255) / 256;
    int wBlocks   = (DDIM * DDIM / 4 + 255) / 256;
    int scBlocks  = (NCHAIN * CHUNKS) / 256;   // 512

    #define SPLIT_W(srcp) split_kernel<<<wBlocks, 256>>>(srcp, Wh, Wl, DDIM * DDIM / 4)
    #define GEMM(inH, inL, biasp, addq, outp, da, sh, sl) \
        mma_gemm_kernel<<<gg, 512, GEMM_SMEM>>>(inH, inL, Wh, Wl, biasp, addq, outp, da, sh, sl)

    // 1) A0 = split(rmsnorm(x, g1))
    rmsnorm_split_kernel<<<MROWS, 256>>>(x, g1, A0h, A0l);
    // 2) lin = xn @ W_lin^T + b_lin ; A1 = split(lin)
    SPLIT_W(W_lin); GEMM(A0h, A0l, b_lin, x, lin, 0, A1h, A1l);
    // 3) rg = lin @ W_conv^T + b_conv ; A0 = split(rg)
    SPLIT_W(W_conv); GEMM(A1h, A1l, b_conv, x, rg, 0, A0h, A0l);
    // 4) rt = rg @ Wa^T + ba ; it = rg @ Wx^T + bx
    SPLIT_W(Wa); GEMM(A0h, A0l, ba, x, rt, 0, (__nv_bfloat16*)nullptr, (__nv_bfloat16*)nullptr);
    SPLIT_W(Wx); GEMM(A0h, A0l, bx, x, it, 0, (__nv_bfloat16*)nullptr, (__nv_bfloat16*)nullptr);
    // 5-7) chunked scan with fused gateprep + fused gelu(lin)*h + split
    scan1_kernel<<<scBlocks, 256>>>(rt, it, rg, Lam, hl, Acar, Hcar);
    scan2_kernel<<<NCHAIN / 256, 256>>>(Acar, Hcar, carry);
    scan3_kernel<<<scBlocks, 256>>>(rt, hl, carry, lin, Lam, A1h, A1l);
    // 8) res = (gelu(lin)*h) @ W_lin2^T + b_lin2 + x
    SPLIT_W(W_lin2); GEMM(A1h, A1l, b_lin2, x, res, 1, (__nv_bfloat16*)nullptr, (__nv_bfloat16*)nullptr);
    // 9) A0 = split(rmsnorm(res, g2))
    rmsnorm_split_kernel<<<MROWS, 256>>>(res, g2, A0h, A0l);
    // 10) rt = xm @ W1^T + b1 ; it = xm @ W2^T + b2
    SPLIT_W(W1); GEMM(A0h, A0l, b1, x, rt, 0, (__nv_bfloat16*)nullptr, (__nv_bfloat16*)nullptr);
    SPLIT_W(W2); GEMM(A0h, A0l, b2, x, it, 0, (__nv_bfloat16*)nullptr, (__nv_bfloat16*)nullptr);
    // 11) A1 = split(gelu(sigmoid(rt)) * it)
    comb_split_kernel<<<ewBlocks, 256>>>(rt, it, A1h, A1l);
    // 12) out = combined @ W3^T + b3 + res
    SPLIT_W(W3); GEMM(A1h, A1l, b3, res, out, 1, (__nv_bfloat16*)nullptr, (__nv_bfloat16*)nullptr);

    (void)in_sizes; (void)n_in; (void)out_size;
}

// round 7
// speedup vs baseline: 1.0875x; 1.0875x over previous
#include <cuda_runtime.h>
#include <cuda_bf16.h>
#include <math.h>
#include <cstdint>

// Problem dims
#define MROWS 16384   // B*T = 4*4096
#define DDIM  1024
#define TLEN  4096
#define CHUNKS 32
#define CHLEN  (TLEN / CHUNKS)   // 128
#define NCHAIN 4096              // B * D

// ---------------- scratch (device globals; no allocation allowed) ----------
__device__ float g_lin[MROWS * DDIM];
__device__ float g_rg [MROWS * DDIM];
__device__ float g_rt [MROWS * DDIM];
__device__ float g_it [MROWS * DDIM];
__device__ float g_res[MROWS * DDIM];
__device__ float g_hl [MROWS * DDIM];
__device__ __nv_bfloat16 g_A0h[MROWS * DDIM];
__device__ __nv_bfloat16 g_A0l[MROWS * DDIM];
__device__ __nv_bfloat16 g_A1h[MROWS * DDIM];
__device__ __nv_bfloat16 g_A1l[MROWS * DDIM];
__device__ __nv_bfloat16 g_Wh[2 * DDIM * DDIM];   // up to 2 stacked weights
__device__ __nv_bfloat16 g_Wl[2 * DDIM * DDIM];
__device__ float g_Acar[NCHAIN * CHUNKS];
__device__ float g_Hcar[NCHAIN * CHUNKS];
__device__ float g_carry[NCHAIN * CHUNKS];

// ---------------- base-ISA tensor helpers ----------------------------------
__device__ __forceinline__ uint32_t smem_to_u32(const void* p) {
    uint32_t a;
    asm("{ .reg .u64 t; cvta.to.shared.u64 t, %1; cvt.u32.u64 %0, t; }"
        : "=r"(a) : "l"(p));
    return a;
}
__device__ __forceinline__ void cpasync16(uint32_t dst, const void* src) {
    asm volatile("cp.async.cg.shared.global [%0], [%1], 16;"
                 :: "r"(dst), "l"(src) : "memory");
}
#define CP_COMMIT() asm volatile("cp.async.commit_group;" ::: "memory")
#define CP_WAIT(n)  asm volatile("cp.async.wait_group %0;" :: "n"(n) : "memory")

__device__ __forceinline__ void ldsm4(uint32_t addr, uint32_t* r) {
    asm volatile("ldmatrix.sync.aligned.m8n8.x4.shared.b16 {%0,%1,%2,%3}, [%4];"
                 : "=r"(r[0]), "=r"(r[1]), "=r"(r[2]), "=r"(r[3]) : "r"(addr));
}
__device__ __forceinline__ void mma16816(float* c, const uint32_t* a, const uint32_t* b) {
    asm volatile(
        "mma.sync.aligned.m16n8k16.row.col.f32.bf16.bf16.f32 "
        "{%0,%1,%2,%3}, {%4,%5,%6,%7}, {%8,%9}, {%0,%1,%2,%3};"
        : "+f"(c[0]), "+f"(c[1]), "+f"(c[2]), "+f"(c[3])
        : "r"(a[0]), "r"(a[1]), "r"(a[2]), "r"(a[3]), "r"(b[0]), "r"(b[1]));
}

// ---------------- math helpers ---------------------------------------------
__device__ __forceinline__ float gelu_exact(float x) {
    return 0.5f * x * (1.0f + erff(x * 0.70710678118654752440f));
}
__device__ __forceinline__ float sigmoidf_(float x) {
    return 1.0f / (1.0f + expf(-x));
}
__device__ __forceinline__ void split2(float a, float b,
                                       __nv_bfloat162& h, __nv_bfloat162& l) {
    h = __floats2bfloat162_rn(a, b);
    l = __floats2bfloat162_rn(a - __low2float(h), b - __high2float(h));
}

// ---------------- fp32 -> (hi, lo) bf16 split (weights) --------------------
__global__ void split_kernel(const float* __restrict__ src,
                             __nv_bfloat16* __restrict__ hi,
                             __nv_bfloat16* __restrict__ lo, int n4) {
    int i = blockIdx.x * 256 + threadIdx.x;
    if (i >= n4) return;
    float4 v = ((const float4*)src)[i];
    __nv_bfloat162 h01, l01, h23, l23;
    split2(v.x, v.y, h01, l01);
    split2(v.z, v.w, h23, l23);
    ((__nv_bfloat162*)hi)[2 * i]     = h01;
    ((__nv_bfloat162*)hi)[2 * i + 1] = h23;
    ((__nv_bfloat162*)lo)[2 * i]     = l01;
    ((__nv_bfloat162*)lo)[2 * i + 1] = l23;
}

// ---------------- split-bf16 mma.sync GEMM ---------------------------------
// C[M,N] = (Ah+Al)[M,K] @ (Bh+Bl)[N,K]^T + bias (+ add), fp32 accumulate.
// CTA tile 128x64, K-chunk 64, 2-stage cp.async pipeline, 256 threads,
// 2 CTAs/SM. N may be 1024 (single) or 2048 (two stacked weights: columns
// >=1024 go to C2/bias2). Optional bf16-split output (single-N only).
#define TILE_A_BYTES 16384           // 128 x 64 bf16
#define TILE_B_BYTES 8192            // 64 x 64 bf16
#define STAGE_BYTES  49152           // Ah, Al, Bh, Bl
#define NSTAGE 2
#define NCHUNK (DDIM / 64)           // 16

__device__ __forceinline__ uint32_t swaddr(uint32_t tile, uint32_t row, uint32_t kb) {
    uint32_t off = row * 128u + kb;
    return tile + (off ^ ((off >> 3) & 0x70u));
}

__global__ void __launch_bounds__(256, 2)
mma_gemm_kernel(const __nv_bfloat16* __restrict__ Ah, const __nv_bfloat16* __restrict__ Al,
                const __nv_bfloat16* __restrict__ Bh, const __nv_bfloat16* __restrict__ Bl,
                const float* __restrict__ bias, const float* __restrict__ addp,
                float* __restrict__ C, int doAdd,
                __nv_bfloat16* __restrict__ Sh, __nv_bfloat16* __restrict__ Sl,
                const float* __restrict__ bias2, float* __restrict__ C2) {
    extern __shared__ __align__(1024) char smem_raw[];
    uint32_t smem0 = smem_to_u32(smem_raw);
    uint32_t tbase = (smem0 + 1023u) & ~1023u;

    int tid = threadIdx.x;
    int wid = tid >> 5;
    int lane = tid & 31;
    int m0 = blockIdx.y * 128;
    int n0 = blockIdx.x * 64;       // 0..N-64 (N = 1024 or 2048)

    // ---- producer mapping: 12 x 16B vecs per thread per stage ----
    int row_base = tid >> 3;
    int col = tid & 7;
    const char* srcb[12];
    uint32_t stsoff[12];
    {
        const char* aBase[2] = { (const char*)(Ah + (size_t)m0 * DDIM),
                                 (const char*)(Al + (size_t)m0 * DDIM) };
        const char* bBase[2] = { (const char*)(Bh + (size_t)n0 * DDIM),
                                 (const char*)(Bl + (size_t)n0 * DDIM) };
        #pragma unroll
        for (int i = 0; i < 8; i++) {
            uint32_t rr = (uint32_t)row_base + 32u * (i & 3);
            srcb[i] = aBase[i >> 2] + (size_t)rr * 2048 + col * 16;
            uint32_t off = rr * 128u + (uint32_t)col * 16u;
            stsoff[i] = (uint32_t)(i >> 2) * TILE_A_BYTES + (off ^ ((off >> 3) & 0x70u));
        }
        #pragma unroll
        for (int i = 8; i < 12; i++) {
            uint32_t rr = (uint32_t)row_base + 32u * ((i - 8) & 1);
            srcb[i] = bBase[(i - 8) >> 1] + (size_t)rr * 2048 + col * 16;
            uint32_t off = rr * 128u + (uint32_t)col * 16u;
            stsoff[i] = 2u * TILE_A_BYTES + (uint32_t)((i - 8) >> 1) * TILE_B_BYTES
                        + (off ^ ((off >> 3) & 0x70u));
        }
    }

    #define ISSUE_STAGE(buf, chunk) do { \
        uint32_t db_ = tbase + (uint32_t)(buf) * STAGE_BYTES; \
        _Pragma("unroll") \
        for (int i_ = 0; i_ < 12; i_++) \
            cpasync16(db_ + stsoff[i_], srcb[i_] + (size_t)(chunk) * 128); \
        CP_COMMIT(); \
    } while (0)

    // ---- consumer mapping: 8 warps, warp tile 32x32 (4 M x 2 N) ----
    int warp_m = wid & 3;
    int warp_n = wid >> 2;
    uint32_t ar  = (uint32_t)((lane & 7) + ((lane >> 3) & 1) * 8);
    uint32_t akb = (uint32_t)(((lane >> 4) & 1) * 16);
    uint32_t br  = (uint32_t)((lane & 7) + ((lane >> 4) & 1) * 8);
    uint32_t bkb = (uint32_t)(((lane >> 3) & 1) * 16);

    float acc[2][4][4];
    #pragma unroll
    for (int i = 0; i < 2; i++)
        #pragma unroll
        for (int j = 0; j < 4; j++)
            #pragma unroll
            for (int q = 0; q < 4; q++) acc[i][j][q] = 0.0f;

    ISSUE_STAGE(0, 0);

    for (int c = 0; c < NCHUNK; c++) {
        CP_WAIT(0);
        __syncthreads();
        if (c + 1 < NCHUNK) ISSUE_STAGE((c + 1) & 1, c + 1);

        uint32_t sb = tbase + (uint32_t)(c & 1) * STAGE_BYTES;
        uint32_t tAh = sb;
        uint32_t tAl = sb + TILE_A_BYTES;
        uint32_t tBh = sb + 2 * TILE_A_BYTES;
        uint32_t tBl = sb + 2 * TILE_A_BYTES + TILE_B_BYTES;

        #pragma unroll
        for (int k16 = 0; k16 < 4; k16++) {
            uint32_t kb = (uint32_t)k16 * 32u;
            uint32_t ah[2][4], al[2][4], bh[2][4], bl[2][4];
            #pragma unroll
            for (int mt = 0; mt < 2; mt++)
                ldsm4(swaddr(tAh, (uint32_t)(warp_m * 32 + mt * 16) + ar, kb + akb), ah[mt]);
            #pragma unroll
            for (int p = 0; p < 2; p++)
                ldsm4(swaddr(tBh, (uint32_t)(warp_n * 32 + p * 16) + br, kb + bkb), bh[p]);
            // term 1: Ah @ Bh
            #pragma unroll
            for (int mt = 0; mt < 2; mt++)
                #pragma unroll
                for (int p = 0; p < 2; p++) {
                    mma16816(acc[mt][2 * p],     ah[mt], &bh[p][0]);
                    mma16816(acc[mt][2 * p + 1], ah[mt], &bh[p][2]);
                }
            // term 2: Ah @ Bl
            #pragma unroll
            for (int p = 0; p < 2; p++)
                ldsm4(swaddr(tBl, (uint32_t)(warp_n * 32 + p * 16) + br, kb + bkb), bl[p]);
            #pragma unroll
            for (int mt = 0; mt < 2; mt++)
                #pragma unroll
                for (int p = 0; p < 2; p++) {
                    mma16816(acc[mt][2 * p],     ah[mt], &bl[p][0]);
                    mma16816(acc[mt][2 * p + 1], ah[mt], &bl[p][2]);
                }
            // term 3: Al @ Bh
            #pragma unroll
            for (int mt = 0; mt < 2; mt++)
                ldsm4(swaddr(tAl, (uint32_t)(warp_m * 32 + mt * 16) + ar, kb + akb), al[mt]);
            #pragma unroll
            for (int mt = 0; mt < 2; mt++)
                #pragma unroll
                for (int p = 0; p < 2; p++) {
                    mma16816(acc[mt][2 * p],     al[mt], &bh[p][0]);
                    mma16816(acc[mt][2 * p + 1], al[mt], &bh[p][2]);
                }
        }
    }

    // ---- epilogue ----
    float* Co = C;
    const float* bp = bias;
    if (n0 >= 1024) { Co = C2; bp = bias2; }
    int nbase = n0 & 1023;
    int lm = lane >> 2;
    int lc = (lane & 3) * 2;
    int cm = m0 + warp_m * 32;
    int cn = nbase + warp_n * 32;
    #pragma unroll
    for (int mt = 0; mt < 2; mt++) {
        #pragma unroll
        for (int nt = 0; nt < 4; nt++) {
            int r0 = cm + mt * 16 + lm;
            int cc = cn + nt * 8 + lc;
            float2 bv = *(const float2*)&bp[cc];
            float* a = acc[mt][nt];
            float2 o0 = make_float2(a[0] + bv.x, a[1] + bv.y);
            float2 o1 = make_float2(a[2] + bv.x, a[3] + bv.y);
            size_t off0 = (size_t)r0 * DDIM + cc;
            size_t off1 = (size_t)(r0 + 8) * DDIM + cc;
            if (doAdd) {
                float2 q0 = *(const float2*)(addp + off0);
                float2 q1 = *(const float2*)(addp + off1);
                o0.x += q0.x; o0.y += q0.y;
                o1.x += q1.x; o1.y += q1.y;
            }
            *(float2*)(Co + off0) = o0;
            *(float2*)(Co + off1) = o1;
            if (Sh) {
                __nv_bfloat162 h0, l0, h1, l1;
                split2(o0.x, o0.y, h0, l0);
                split2(o1.x, o1.y, h1, l1);
                *(__nv_bfloat162*)(Sh + off0) = h0;
                *(__nv_bfloat162*)(Sl + off0) = l0;
                *(__nv_bfloat162*)(Sh + off1) = h1;
                *(__nv_bfloat162*)(Sl + off1) = l1;
            }
        }
    }
}

// ---------------- rmsnorm -> bf16 split ------------------------------------
__global__ void rmsnorm_split_kernel(const float* __restrict__ x,
                                     const float* __restrict__ gw,
                                     __nv_bfloat16* __restrict__ Sh,
                                     __nv_bfloat16* __restrict__ Sl) {
    int row = blockIdx.x;
    const float4* xr = (const float4*)(x + (size_t)row * DDIM);
    float4 v = xr[threadIdx.x];
    float ss = v.x * v.x + v.y * v.y + v.z * v.z + v.w * v.w;
    #pragma unroll
    for (int o = 16; o > 0; o >>= 1) ss += __shfl_xor_sync(0xffffffffu, ss, o);
    __shared__ float sred[8];
    if ((threadIdx.x & 31) == 0) sred[threadIdx.x >> 5] = ss;
    __syncthreads();
    float total = 0.0f;
    #pragma unroll
    for (int i = 0; i < 8; i++) total += sred[i];
    float n = fmaxf(sqrtf(total), 1e-12f);
    float s = 32.0f / n;
    float4 g = ((const float4*)gw)[threadIdx.x];
    float o0 = v.x * s * g.x, o1 = v.y * s * g.y;
    float o2 = v.z * s * g.z, o3 = v.w * s * g.w;
    __nv_bfloat162 h01, l01, h23, l23;
    split2(o0, o1, h01, l01);
    split2(o2, o3, h23, l23);
    size_t base2 = (size_t)row * (DDIM / 2) + threadIdx.x * 2;
    ((__nv_bfloat162*)Sh)[base2]     = h01;
    ((__nv_bfloat162*)Sh)[base2 + 1] = h23;
    ((__nv_bfloat162*)Sl)[base2]     = l01;
    ((__nv_bfloat162*)Sl)[base2 + 1] = l23;
}

// ---------------- chunked RG-LRU scan --------------------------------------
__global__ void scan1_kernel(const float* __restrict__ rt, const float* __restrict__ it,
                             const float* __restrict__ rg, const float* __restrict__ Lam,
                             float* __restrict__ hl,
                             float* __restrict__ Acar, float* __restrict__ Hcar) {
    int i = blockIdx.x * 256 + threadIdx.x;     // 0 .. 131071
    int chain = i & (NCHAIN - 1);
    int chunk = i >> 12;
    int b = chain >> 10, d = chain & (DDIM - 1);
    size_t base = ((size_t)b * TLEN + (size_t)chunk * CHLEN) * DDIM + d;
    float la = -log1pf(expf(-Lam[d]));
    float h = 0.0f, P = 1.0f;
    for (int t = 0; t < CHLEN; t++) {
        size_t a_ = base + (size_t)t * DDIM;
        float r  = rt[a_];
        float iv = it[a_];
        float xv = rg[a_];
        float a = expf(la * sigmoidf_(r) * 0.125f);
        float g = sqrtf(fmaxf(1.0f - a * a, 0.0f)) * sigmoidf_(iv) * xv;
        h = fmaf(a, h, g);
        P *= a;
        hl[a_] = h;
    }
    Acar[i] = P;
    Hcar[i] = h;
}

__global__ void scan2_kernel(const float* __restrict__ Acar, const float* __restrict__ Hcar,
                             float* __restrict__ carry) {
    int chain = blockIdx.x * 256 + threadIdx.x;   // 0..4095
    float h = 0.0f;
    #pragma unroll
    for (int c = 0; c < CHUNKS; c++) {
        int idx = c * NCHAIN + chain;
        carry[idx] = h;
        h = fmaf(Acar[idx], h, Hcar[idx]);
    }
}

__global__ void scan3_kernel(const float* __restrict__ rt, const float* __restrict__ hl,
                             const float* __restrict__ carry, const float* __restrict__ lin,
                             const float* __restrict__ Lam,
                             __nv_bfloat16* __restrict__ Sh, __nv_bfloat16* __restrict__ Sl) {
    int i = blockIdx.x * 256 + threadIdx.x;
    int chain = i & (NCHAIN - 1);
    int chunk = i >> 12;
    int b = chain >> 10, d = chain & (DDIM - 1);
    size_t base = ((size_t)b * TLEN + (size_t)chunk * CHLEN) * DDIM + d;
    float la = -log1pf(expf(-Lam[d]));
    float cin = carry[i];
    float P = 1.0f;
    for (int t = 0; t < CHLEN; t++) {
        size_t a_ = base + (size_t)t * DDIM;
        float r = rt[a_];
        float a = expf(la * sigmoidf_(r) * 0.125f);
        P *= a;
        float h = fmaf(P, cin, hl[a_]);
        float l = lin[a_];
        float o = gelu_exact(l) * h;
        __nv_bfloat16 bh = __float2bfloat16_rn(o);
        __nv_bfloat16 bl = __float2bfloat16_rn(o - __bfloat162float(bh));
        Sh[a_] = bh;
        Sl[a_] = bl;
    }
}

// ---------------- gelu(sigmoid(t1)) * t2 -> bf16 split ---------------------
__global__ void comb_split_kernel(const float* __restrict__ t1,
                                  const float* __restrict__ t2,
                                  __nv_bfloat16* __restrict__ Sh,
                                  __nv_bfloat16* __restrict__ Sl) {
    int i = blockIdx.x * blockDim.x + threadIdx.x;
    if (i >= MROWS * DDIM / 4) return;
    float4 a = ((const float4*)t1)[i];
    float4 b = ((const float4*)t2)[i];
    float o0 = gelu_exact(sigmoidf_(a.x)) * b.x;
    float o1 = gelu_exact(sigmoidf_(a.y)) * b.y;
    float o2 = gelu_exact(sigmoidf_(a.z)) * b.z;
    float o3 = gelu_exact(sigmoidf_(a.w)) * b.w;
    __nv_bfloat162 h01, l01, h23, l23;
    split2(o0, o1, h01, l01);
    split2(o2, o3, h23, l23);
    ((__nv_bfloat162*)Sh)[2 * i]     = h01;
    ((__nv_bfloat162*)Sh)[2 * i + 1] = h23;
    ((__nv_bfloat162*)Sl)[2 * i]     = l01;
    ((__nv_bfloat162*)Sl)[2 * i + 1] = l23;
}

// ---------------- launch ---------------------------------------------------
extern "C" void kernel_launch(void* const* d_in, const int* in_sizes, int n_in,
                              void* d_out, int out_size) {
    const float* x      = (const float*)d_in[0];
    const float* g1     = (const float*)d_in[1];
    const float* g2     = (const float*)d_in[2];
    const float* W_lin  = (const float*)d_in[3];
    const float* b_lin  = (const float*)d_in[4];
    const float* W_conv = (const float*)d_in[5];
    const float* b_conv = (const float*)d_in[6];
    const float* W_lin2 = (const float*)d_in[7];
    const float* b_lin2 = (const float*)d_in[8];
    const float* Wa     = (const float*)d_in[9];
    const float* ba     = (const float*)d_in[10];
    const float* Wx     = (const float*)d_in[11];
    const float* bx     = (const float*)d_in[12];
    const float* Lam    = (const float*)d_in[13];
    const float* W1     = (const float*)d_in[14];
    const float* b1     = (const float*)d_in[15];
    const float* W2     = (const float*)d_in[16];
    const float* b2     = (const float*)d_in[17];
    const float* W3     = (const float*)d_in[18];
    const float* b3     = (const float*)d_in[19];
    float* out = (float*)d_out;

    float *lin, *rg, *rt, *it, *res, *hl, *Acar, *Hcar, *carry;
    __nv_bfloat16 *A0h, *A0l, *A1h, *A1l, *Wh, *Wl;
    cudaGetSymbolAddress((void**)&lin, g_lin);
    cudaGetSymbolAddress((void**)&rg,  g_rg);
    cudaGetSymbolAddress((void**)&rt,  g_rt);
    cudaGetSymbolAddress((void**)&it,  g_it);
    cudaGetSymbolAddress((void**)&res, g_res);
    cudaGetSymbolAddress((void**)&hl,  g_hl);
    cudaGetSymbolAddress((void**)&Acar, g_Acar);
    cudaGetSymbolAddress((void**)&Hcar, g_Hcar);
    cudaGetSymbolAddress((void**)&carry, g_carry);
    cudaGetSymbolAddress((void**)&A0h, g_A0h);
    cudaGetSymbolAddress((void**)&A0l, g_A0l);
    cudaGetSymbolAddress((void**)&A1h, g_A1h);
    cudaGetSymbolAddress((void**)&A1l, g_A1l);
    cudaGetSymbolAddress((void**)&Wh,  g_Wh);
    cudaGetSymbolAddress((void**)&Wl,  g_Wl);

    const int GEMM_SMEM = NSTAGE * STAGE_BYTES + 1024;   // 99328
    cudaFuncSetAttribute(mma_gemm_kernel,
                         cudaFuncAttributeMaxDynamicSharedMemorySize, GEMM_SMEM);

    dim3 gg1(DDIM / 64, MROWS / 128);        // (16, 128)  N=1024
    dim3 gg2(2 * DDIM / 64, MROWS / 128);    // (32, 128)  N=2048
    int ewBlocks  = (MROWS * DDIM / 4 + 255) / 256;
    int wBlocks   = (DDIM * DDIM / 4 + 255) / 256;
    int scBlocks  = (NCHAIN * CHUNKS) / 256;   // 512
    const int WN = DDIM * DDIM;

    #define SPLIT_W1(srcp) split_kernel<<<wBlocks, 256>>>(srcp, Wh, Wl, WN / 4)
    #define SPLIT_W2(srcp) split_kernel<<<wBlocks, 256>>>(srcp, Wh + WN, Wl + WN, WN / 4)
    #define GEMM1(inH, inL, biasp, addq, outp, da, sh, sl) \
        mma_gemm_kernel<<<gg1, 256, GEMM_SMEM>>>(inH, inL, Wh, Wl, biasp, addq, outp, da, sh, sl, \
                                                 (const float*)nullptr, (float*)nullptr)
    #define GEMM2(inH, inL, biaspA, outA, biaspB, outB) \
        mma_gemm_kernel<<<gg2, 256, GEMM_SMEM>>>(inH, inL, Wh, Wl, biaspA, x, outA, 0, \
                                                 (__nv_bfloat16*)nullptr, (__nv_bfloat16*)nullptr, \
                                                 biaspB, outB)

    // 1) A0 = split(rmsnorm(x, g1))
    rmsnorm_split_kernel<<<MROWS, 256>>>(x, g1, A0h, A0l);
    // 2) lin = xn @ W_lin^T + b_lin ; A1 = split(lin)
    SPLIT_W1(W_lin); GEMM1(A0h, A0l, b_lin, x, lin, 0, A1h, A1l);
    // 3) rg = lin @ W_conv^T + b_conv ; A0 = split(rg)
    SPLIT_W1(W_conv); GEMM1(A1h, A1l, b_conv, x, rg, 0, A0h, A0l);
    // 4) merged: rt = rg @ Wa^T + ba ; it = rg @ Wx^T + bx
    SPLIT_W1(Wa); SPLIT_W2(Wx);
    GEMM2(A0h, A0l, ba, rt, bx, it);
    // 5-7) chunked scan with fused gateprep + fused gelu(lin)*h + split
    scan1_kernel<<<scBlocks, 256>>>(rt, it, rg, Lam, hl, Acar, Hcar);
    scan2_kernel<<<NCHAIN / 256, 256>>>(Acar, Hcar, carry);
    scan3_kernel<<<scBlocks, 256>>>(rt, hl, carry, lin, Lam, A1h, A1l);
    // 8) res = (gelu(lin)*h) @ W_lin2^T + b_lin2 + x
    SPLIT_W1(W_lin2); GEMM1(A1h, A1l, b_lin2, x, res, 1, (__nv_bfloat16*)nullptr, (__nv_bfloat16*)nullptr);
    // 9) A0 = split(rmsnorm(res, g2))
    rmsnorm_split_kernel<<<MROWS, 256>>>(res, g2, A0h, A0l);
    // 10) merged: rt = xm @ W1^T + b1 ; it = xm @ W2^T + b2
    SPLIT_W1(W1); SPLIT_W2(W2);
    GEMM2(A0h, A0l, b1, rt, b2, it);
    // 11) A1 = split(gelu(sigmoid(rt)) * it)
    comb_split_kernel<<<ewBlocks, 256>>>(rt, it, A1h, A1l);
    // 12) out = combined @ W3^T + b3 + res
    SPLIT_W1(W3); GEMM1(A1h, A1l, b3, res, out, 1, (__nv_bfloat16*)nullptr, (__nv_bfloat16*)nullptr);

    (void)in_sizes; (void)n_in; (void)out_size;
}

// round 8
// speedup vs baseline: 1.2463x; 1.1460x over previous
#include <cuda_runtime.h>
#include <cuda_bf16.h>
#include <cuda_fp16.h>
#include <math.h>
#include <cstdint>

// Problem dims
#define MROWS 16384   // B*T = 4*4096
#define DDIM  1024
#define TLEN  4096
#define CHUNKS 32
#define CHLEN  (TLEN / CHUNKS)   // 128
#define NCHAIN 4096              // B * D

// ---------------- scratch (device globals; no allocation allowed) ----------
__device__ float g_lin[MROWS * DDIM];
__device__ float g_rg [MROWS * DDIM];
__device__ float g_rt [MROWS * DDIM];
__device__ float g_it [MROWS * DDIM];
__device__ float g_res[MROWS * DDIM];
__device__ float g_hl [MROWS * DDIM];
__device__ __nv_bfloat16 g_A1h[MROWS * DDIM];
__device__ __nv_bfloat16 g_A1l[MROWS * DDIM];
__device__ __nv_bfloat16 g_A0h[MROWS * DDIM];
__device__ __nv_bfloat16 g_A0l[MROWS * DDIM];
__device__ __half g_Af[MROWS * DDIM];
__device__ __nv_bfloat16 g_Wh[DDIM * DDIM];
__device__ __nv_bfloat16 g_Wl[DDIM * DDIM];
__device__ __half g_Wfh[2 * DDIM * DDIM];
__device__ __half g_Wfl[2 * DDIM * DDIM];
__device__ float g_Acar[NCHAIN * CHUNKS];
__device__ float g_Hcar[NCHAIN * CHUNKS];
__device__ float g_carry[NCHAIN * CHUNKS];

// ---------------- base-ISA tensor helpers ----------------------------------
__device__ __forceinline__ uint32_t smem_to_u32(const void* p) {
    uint32_t a;
    asm("{ .reg .u64 t; cvta.to.shared.u64 t, %1; cvt.u32.u64 %0, t; }"
        : "=r"(a) : "l"(p));
    return a;
}
__device__ __forceinline__ void cpasync16(uint32_t dst, const void* src) {
    asm volatile("cp.async.cg.shared.global [%0], [%1], 16;"
                 :: "r"(dst), "l"(src) : "memory");
}
#define CP_COMMIT() asm volatile("cp.async.commit_group;" ::: "memory")
#define CP_WAIT(n)  asm volatile("cp.async.wait_group %0;" :: "n"(n) : "memory")

__device__ __forceinline__ void ldsm4(uint32_t addr, uint32_t* r) {
    asm volatile("ldmatrix.sync.aligned.m8n8.x4.shared.b16 {%0,%1,%2,%3}, [%4];"
                 : "=r"(r[0]), "=r"(r[1]), "=r"(r[2]), "=r"(r[3]) : "r"(addr));
}
__device__ __forceinline__ void mma16816(float* c, const uint32_t* a, const uint32_t* b) {
    asm volatile(
        "mma.sync.aligned.m16n8k16.row.col.f32.bf16.bf16.f32 "
        "{%0,%1,%2,%3}, {%4,%5,%6,%7}, {%8,%9}, {%0,%1,%2,%3};"
        : "+f"(c[0]), "+f"(c[1]), "+f"(c[2]), "+f"(c[3])
        : "r"(a[0]), "r"(a[1]), "r"(a[2]), "r"(a[3]), "r"(b[0]), "r"(b[1]));
}
__device__ __forceinline__ void mma16816h(float* c, const uint32_t* a, const uint32_t* b) {
    asm volatile(
        "mma.sync.aligned.m16n8k16.row.col.f32.f16.f16.f32 "
        "{%0,%1,%2,%3}, {%4,%5,%6,%7}, {%8,%9}, {%0,%1,%2,%3};"
        : "+f"(c[0]), "+f"(c[1]), "+f"(c[2]), "+f"(c[3])
        : "r"(a[0]), "r"(a[1]), "r"(a[2]), "r"(a[3]), "r"(b[0]), "r"(b[1]));
}

// ---------------- math helpers ---------------------------------------------
__device__ __forceinline__ float gelu_exact(float x) {
    return 0.5f * x * (1.0f + erff(x * 0.70710678118654752440f));
}
__device__ __forceinline__ float sigmoidf_(float x) {
    return 1.0f / (1.0f + expf(-x));
}
__device__ __forceinline__ void split2(float a, float b,
                                       __nv_bfloat162& h, __nv_bfloat162& l) {
    h = __floats2bfloat162_rn(a, b);
    l = __floats2bfloat162_rn(a - __low2float(h), b - __high2float(h));
}
__device__ __forceinline__ void split2h(float a, float b,
                                        __half2& h, __half2& l) {
    h = __floats2half2_rn(a, b);
    l = __floats2half2_rn(a - __low2float(h), b - __high2float(h));
}

// ---------------- fp32 -> (hi, lo) bf16 split (weights) --------------------
__global__ void split_kernel(const float* __restrict__ src,
                             __nv_bfloat16* __restrict__ hi,
                             __nv_bfloat16* __restrict__ lo, int n4) {
    int i = blockIdx.x * 256 + threadIdx.x;
    if (i >= n4) return;
    float4 v = ((const float4*)src)[i];
    __nv_bfloat162 h01, l01, h23, l23;
    split2(v.x, v.y, h01, l01);
    split2(v.z, v.w, h23, l23);
    ((__nv_bfloat162*)hi)[2 * i]     = h01;
    ((__nv_bfloat162*)hi)[2 * i + 1] = h23;
    ((__nv_bfloat162*)lo)[2 * i]     = l01;
    ((__nv_bfloat162*)lo)[2 * i + 1] = l23;
}

// ---------------- fp32 -> (hi, lo) fp16 split (gate weights) ---------------
__global__ void split_f16_kernel(const float* __restrict__ src,
                                 __half* __restrict__ hi,
                                 __half* __restrict__ lo, int n4) {
    int i = blockIdx.x * 256 + threadIdx.x;
    if (i >= n4) return;
    float4 v = ((const float4*)src)[i];
    __half2 h01, l01, h23, l23;
    split2h(v.x, v.y, h01, l01);
    split2h(v.z, v.w, h23, l23);
    ((__half2*)hi)[2 * i]     = h01;
    ((__half2*)hi)[2 * i + 1] = h23;
    ((__half2*)lo)[2 * i]     = l01;
    ((__half2*)lo)[2 * i + 1] = l23;
}

// ---------------- split-bf16 mma.sync GEMM (3-term, main path) -------------
// C[M,1024] = (Ah+Al)[M,K] @ (Bh+Bl)[1024,K]^T + bias (+ add).
// CTA tile 128x64, K-chunk 64, 2-stage, 256 threads, 2 CTAs/SM.
// Optional outputs: bf16 split (Sh,Sl) and/or fp16 single (Sf).
#define TILE_A_BYTES 16384           // 128 x 64 bf16
#define TILE_B_BYTES 8192            // 64 x 64 bf16
#define STAGE_BYTES  49152           // Ah, Al, Bh, Bl
#define NCHUNK (DDIM / 64)           // 16

__device__ __forceinline__ uint32_t swaddr(uint32_t tile, uint32_t row, uint32_t kb) {
    uint32_t off = row * 128u + kb;
    return tile + (off ^ ((off >> 3) & 0x70u));
}

__global__ void __launch_bounds__(256, 2)
mma_gemm_kernel(const __nv_bfloat16* __restrict__ Ah, const __nv_bfloat16* __restrict__ Al,
                const __nv_bfloat16* __restrict__ Bh, const __nv_bfloat16* __restrict__ Bl,
                const float* __restrict__ bias, const float* __restrict__ addp,
                float* __restrict__ C, int doAdd,
                __nv_bfloat16* __restrict__ Sh, __nv_bfloat16* __restrict__ Sl,
                __half* __restrict__ Sf) {
    extern __shared__ __align__(1024) char smem_raw[];
    uint32_t smem0 = smem_to_u32(smem_raw);
    uint32_t tbase = (smem0 + 1023u) & ~1023u;

    int tid = threadIdx.x;
    int wid = tid >> 5;
    int lane = tid & 31;
    int m0 = blockIdx.y * 128;
    int n0 = blockIdx.x * 64;

    int row_base = tid >> 3;
    int col = tid & 7;
    const char* srcb[12];
    uint32_t stsoff[12];
    {
        const char* aBase[2] = { (const char*)(Ah + (size_t)m0 * DDIM),
                                 (const char*)(Al + (size_t)m0 * DDIM) };
        const char* bBase[2] = { (const char*)(Bh + (size_t)n0 * DDIM),
                                 (const char*)(Bl + (size_t)n0 * DDIM) };
        #pragma unroll
        for (int i = 0; i < 8; i++) {
            uint32_t rr = (uint32_t)row_base + 32u * (i & 3);
            srcb[i] = aBase[i >> 2] + (size_t)rr * 2048 + col * 16;
            uint32_t off = rr * 128u + (uint32_t)col * 16u;
            stsoff[i] = (uint32_t)(i >> 2) * TILE_A_BYTES + (off ^ ((off >> 3) & 0x70u));
        }
        #pragma unroll
        for (int i = 8; i < 12; i++) {
            uint32_t rr = (uint32_t)row_base + 32u * ((i - 8) & 1);
            srcb[i] = bBase[(i - 8) >> 1] + (size_t)rr * 2048 + col * 16;
            uint32_t off = rr * 128u + (uint32_t)col * 16u;
            stsoff[i] = 2u * TILE_A_BYTES + (uint32_t)((i - 8) >> 1) * TILE_B_BYTES
                        + (off ^ ((off >> 3) & 0x70u));
        }
    }

    #define ISSUE_STAGE(buf, chunk) do { \
        uint32_t db_ = tbase + (uint32_t)(buf) * STAGE_BYTES; \
        _Pragma("unroll") \
        for (int i_ = 0; i_ < 12; i_++) \
            cpasync16(db_ + stsoff[i_], srcb[i_] + (size_t)(chunk) * 128); \
        CP_COMMIT(); \
    } while (0)

    int warp_m = wid & 3;
    int warp_n = wid >> 2;
    uint32_t ar  = (uint32_t)((lane & 7) + ((lane >> 3) & 1) * 8);
    uint32_t akb = (uint32_t)(((lane >> 4) & 1) * 16);
    uint32_t br  = (uint32_t)((lane & 7) + ((lane >> 4) & 1) * 8);
    uint32_t bkb = (uint32_t)(((lane >> 3) & 1) * 16);

    float acc[2][4][4];
    #pragma unroll
    for (int i = 0; i < 2; i++)
        #pragma unroll
        for (int j = 0; j < 4; j++)
            #pragma unroll
            for (int q = 0; q < 4; q++) acc[i][j][q] = 0.0f;

    ISSUE_STAGE(0, 0);

    for (int c = 0; c < NCHUNK; c++) {
        CP_WAIT(0);
        __syncthreads();
        if (c + 1 < NCHUNK) ISSUE_STAGE((c + 1) & 1, c + 1);

        uint32_t sb = tbase + (uint32_t)(c & 1) * STAGE_BYTES;
        uint32_t tAh = sb;
        uint32_t tAl = sb + TILE_A_BYTES;
        uint32_t tBh = sb + 2 * TILE_A_BYTES;
        uint32_t tBl = sb + 2 * TILE_A_BYTES + TILE_B_BYTES;

        #pragma unroll
        for (int k16 = 0; k16 < 4; k16++) {
            uint32_t kb = (uint32_t)k16 * 32u;
            uint32_t ah[2][4], al[2][4], bh[2][4], bl[2][4];
            #pragma unroll
            for (int mt = 0; mt < 2; mt++)
                ldsm4(swaddr(tAh, (uint32_t)(warp_m * 32 + mt * 16) + ar, kb + akb), ah[mt]);
            #pragma unroll
            for (int p = 0; p < 2; p++)
                ldsm4(swaddr(tBh, (uint32_t)(warp_n * 32 + p * 16) + br, kb + bkb), bh[p]);
            #pragma unroll
            for (int mt = 0; mt < 2; mt++)
                #pragma unroll
                for (int p = 0; p < 2; p++) {
                    mma16816(acc[mt][2 * p],     ah[mt], &bh[p][0]);
                    mma16816(acc[mt][2 * p + 1], ah[mt], &bh[p][2]);
                }
            #pragma unroll
            for (int p = 0; p < 2; p++)
                ldsm4(swaddr(tBl, (uint32_t)(warp_n * 32 + p * 16) + br, kb + bkb), bl[p]);
            #pragma unroll
            for (int mt = 0; mt < 2; mt++)
                #pragma unroll
                for (int p = 0; p < 2; p++) {
                    mma16816(acc[mt][2 * p],     ah[mt], &bl[p][0]);
                    mma16816(acc[mt][2 * p + 1], ah[mt], &bl[p][2]);
                }
            #pragma unroll
            for (int mt = 0; mt < 2; mt++)
                ldsm4(swaddr(tAl, (uint32_t)(warp_m * 32 + mt * 16) + ar, kb + akb), al[mt]);
            #pragma unroll
            for (int mt = 0; mt < 2; mt++)
                #pragma unroll
                for (int p = 0; p < 2; p++) {
                    mma16816(acc[mt][2 * p],     al[mt], &bh[p][0]);
                    mma16816(acc[mt][2 * p + 1], al[mt], &bh[p][2]);
                }
        }
    }

    int lm = lane >> 2;
    int lc = (lane & 3) * 2;
    int cm = m0 + warp_m * 32;
    int cn = n0 + warp_n * 32;
    #pragma unroll
    for (int mt = 0; mt < 2; mt++) {
        #pragma unroll
        for (int nt = 0; nt < 4; nt++) {
            int r0 = cm + mt * 16 + lm;
            int cc = cn + nt * 8 + lc;
            float2 bv = *(const float2*)&bias[cc];
            float* a = acc[mt][nt];
            float2 o0 = make_float2(a[0] + bv.x, a[1] + bv.y);
            float2 o1 = make_float2(a[2] + bv.x, a[3] + bv.y);
            size_t off0 = (size_t)r0 * DDIM + cc;
            size_t off1 = (size_t)(r0 + 8) * DDIM + cc;
            if (doAdd) {
                float2 q0 = *(const float2*)(addp + off0);
                float2 q1 = *(const float2*)(addp + off1);
                o0.x += q0.x; o0.y += q0.y;
                o1.x += q1.x; o1.y += q1.y;
            }
            *(float2*)(C + off0) = o0;
            *(float2*)(C + off1) = o1;
            if (Sh) {
                __nv_bfloat162 h0, l0, h1, l1;
                split2(o0.x, o0.y, h0, l0);
                split2(o1.x, o1.y, h1, l1);
                *(__nv_bfloat162*)(Sh + off0) = h0;
                *(__nv_bfloat162*)(Sl + off0) = l0;
                *(__nv_bfloat162*)(Sh + off1) = h1;
                *(__nv_bfloat162*)(Sl + off1) = l1;
            }
            if (Sf) {
                *(__half2*)(Sf + off0) = __floats2half2_rn(o0.x, o0.y);
                *(__half2*)(Sf + off1) = __floats2half2_rn(o1.x, o1.y);
            }
        }
    }
}

// ---------------- fp16 2-term GEMM (gate path, N=2048 double) --------------
// C[:,0:1024]=A@Wh0+Wl0 correction, C2 = cols 1024:2048.
// A single fp16 [M,K]; W split fp16 (Wfh+Wfl) [2048,K].
#define F_TILE_A 16384               // 128 x 64 fp16
#define F_TILE_B 8192                // 64 x 64 fp16
#define F_STAGE  32768               // Af, Bh, Bl

__global__ void __launch_bounds__(256, 2)
mma_gemm_f16_kernel(const __half* __restrict__ Af,
                    const __half* __restrict__ Bh, const __half* __restrict__ Bl,
                    const float* __restrict__ bias, float* __restrict__ C,
                    const float* __restrict__ bias2, float* __restrict__ C2) {
    extern __shared__ __align__(1024) char smem_raw[];
    uint32_t smem0 = smem_to_u32(smem_raw);
    uint32_t tbase = (smem0 + 1023u) & ~1023u;

    int tid = threadIdx.x;
    int wid = tid >> 5;
    int lane = tid & 31;
    int m0 = blockIdx.y * 128;
    int n0 = blockIdx.x * 64;       // 0..2047

    int row_base = tid >> 3;
    int col = tid & 7;
    const char* srcb[8];
    uint32_t stsoff[8];
    {
        const char* aB = (const char*)(Af + (size_t)m0 * DDIM);
        const char* bB[2] = { (const char*)(Bh + (size_t)n0 * DDIM),
                              (const char*)(Bl + (size_t)n0 * DDIM) };
        #pragma unroll
        for (int i = 0; i < 4; i++) {
            uint32_t rr = (uint32_t)row_base + 32u * i;
            srcb[i] = aB + (size_t)rr * 2048 + col * 16;
            uint32_t off = rr * 128u + (uint32_t)col * 16u;
            stsoff[i] = off ^ ((off >> 3) & 0x70u);
        }
        #pragma unroll
        for (int i = 4; i < 8; i++) {
            uint32_t rr = (uint32_t)row_base + 32u * ((i - 4) & 1);
            srcb[i] = bB[(i - 4) >> 1] + (size_t)rr * 2048 + col * 16;
            uint32_t off = rr * 128u + (uint32_t)col * 16u;
            stsoff[i] = F_TILE_A + (uint32_t)((i - 4) >> 1) * F_TILE_B
                        + (off ^ ((off >> 3) & 0x70u));
        }
    }

    #define F_ISSUE(buf, chunk) do { \
        uint32_t db_ = tbase + (uint32_t)(buf) * F_STAGE; \
        _Pragma("unroll") \
        for (int i_ = 0; i_ < 8; i_++) \
            cpasync16(db_ + stsoff[i_], srcb[i_] + (size_t)(chunk) * 128); \
        CP_COMMIT(); \
    } while (0)

    int warp_m = wid & 3;
    int warp_n = wid >> 2;
    uint32_t ar  = (uint32_t)((lane & 7) + ((lane >> 3) & 1) * 8);
    uint32_t akb = (uint32_t)(((lane >> 4) & 1) * 16);
    uint32_t br  = (uint32_t)((lane & 7) + ((lane >> 4) & 1) * 8);
    uint32_t bkb = (uint32_t)(((lane >> 3) & 1) * 16);

    float acc[2][4][4];
    #pragma unroll
    for (int i = 0; i < 2; i++)
        #pragma unroll
        for (int j = 0; j < 4; j++)
            #pragma unroll
            for (int q = 0; q < 4; q++) acc[i][j][q] = 0.0f;

    F_ISSUE(0, 0);

    for (int c = 0; c < NCHUNK; c++) {
        CP_WAIT(0);
        __syncthreads();
        if (c + 1 < NCHUNK) F_ISSUE((c + 1) & 1, c + 1);

        uint32_t sb = tbase + (uint32_t)(c & 1) * F_STAGE;
        uint32_t tAf = sb;
        uint32_t tBh = sb + F_TILE_A;
        uint32_t tBl = sb + F_TILE_A + F_TILE_B;

        #pragma unroll
        for (int k16 = 0; k16 < 4; k16++) {
            uint32_t kb = (uint32_t)k16 * 32u;
            uint32_t af[2][4], bh[2][4], bl[2][4];
            #pragma unroll
            for (int mt = 0; mt < 2; mt++)
                ldsm4(swaddr(tAf, (uint32_t)(warp_m * 32 + mt * 16) + ar, kb + akb), af[mt]);
            #pragma unroll
            for (int p = 0; p < 2; p++)
                ldsm4(swaddr(tBh, (uint32_t)(warp_n * 32 + p * 16) + br, kb + bkb), bh[p]);
            #pragma unroll
            for (int mt = 0; mt < 2; mt++)
                #pragma unroll
                for (int p = 0; p < 2; p++) {
                    mma16816h(acc[mt][2 * p],     af[mt], &bh[p][0]);
                    mma16816h(acc[mt][2 * p + 1], af[mt], &bh[p][2]);
                }
            #pragma unroll
            for (int p = 0; p < 2; p++)
                ldsm4(swaddr(tBl, (uint32_t)(warp_n * 32 + p * 16) + br, kb + bkb), bl[p]);
            #pragma unroll
            for (int mt = 0; mt < 2; mt++)
                #pragma unroll
                for (int p = 0; p < 2; p++) {
                    mma16816h(acc[mt][2 * p],     af[mt], &bl[p][0]);
                    mma16816h(acc[mt][2 * p + 1], af[mt], &bl[p][2]);
                }
        }
    }

    float* Co = C;
    const float* bp = bias;
    if (n0 >= 1024) { Co = C2; bp = bias2; }
    int nbase = n0 & 1023;
    int lm = lane >> 2;
    int lc = (lane & 3) * 2;
    int cm = m0 + warp_m * 32;
    int cn = nbase + warp_n * 32;
    #pragma unroll
    for (int mt = 0; mt < 2; mt++) {
        #pragma unroll
        for (int nt = 0; nt < 4; nt++) {
            int r0 = cm + mt * 16 + lm;
            int cc = cn + nt * 8 + lc;
            float2 bv = *(const float2*)&bp[cc];
            float* a = acc[mt][nt];
            size_t off0 = (size_t)r0 * DDIM + cc;
            size_t off1 = (size_t)(r0 + 8) * DDIM + cc;
            *(float2*)(Co + off0) = make_float2(a[0] + bv.x, a[1] + bv.y);
            *(float2*)(Co + off1) = make_float2(a[2] + bv.x, a[3] + bv.y);
        }
    }
}

// ---------------- rmsnorm -> splits ----------------------------------------
__global__ void rmsnorm_split_kernel(const float* __restrict__ x,
                                     const float* __restrict__ gw,
                                     __nv_bfloat16* __restrict__ Sh,
                                     __nv_bfloat16* __restrict__ Sl,
                                     __half* __restrict__ Sf) {
    int row = blockIdx.x;
    const float4* xr = (const float4*)(x + (size_t)row * DDIM);
    float4 v = xr[threadIdx.x];
    float ss = v.x * v.x + v.y * v.y + v.z * v.z + v.w * v.w;
    #pragma unroll
    for (int o = 16; o > 0; o >>= 1) ss += __shfl_xor_sync(0xffffffffu, ss, o);
    __shared__ float sred[8];
    if ((threadIdx.x & 31) == 0) sred[threadIdx.x >> 5] = ss;
    __syncthreads();
    float total = 0.0f;
    #pragma unroll
    for (int i = 0; i < 8; i++) total += sred[i];
    float n = fmaxf(sqrtf(total), 1e-12f);
    float s = 32.0f / n;
    float4 g = ((const float4*)gw)[threadIdx.x];
    float o0 = v.x * s * g.x, o1 = v.y * s * g.y;
    float o2 = v.z * s * g.z, o3 = v.w * s * g.w;
    size_t base2 = (size_t)row * (DDIM / 2) + threadIdx.x * 2;
    if (Sh) {
        __nv_bfloat162 h01, l01, h23, l23;
        split2(o0, o1, h01, l01);
        split2(o2, o3, h23, l23);
        ((__nv_bfloat162*)Sh)[base2]     = h01;
        ((__nv_bfloat162*)Sh)[base2 + 1] = h23;
        ((__nv_bfloat162*)Sl)[base2]     = l01;
        ((__nv_bfloat162*)Sl)[base2 + 1] = l23;
    }
    if (Sf) {
        ((__half2*)Sf)[base2]     = __floats2half2_rn(o0, o1);
        ((__half2*)Sf)[base2 + 1] = __floats2half2_rn(o2, o3);
    }
}

// ---------------- chunked RG-LRU scan --------------------------------------
__global__ void scan1_kernel(const float* __restrict__ rt, const float* __restrict__ it,
                             const float* __restrict__ rg, const float* __restrict__ Lam,
                             float* __restrict__ hl,
                             float* __restrict__ Acar, float* __restrict__ Hcar) {
    int i = blockIdx.x * 256 + threadIdx.x;     // 0 .. 131071
    int chain = i & (NCHAIN - 1);
    int chunk = i >> 12;
    int b = chain >> 10, d = chain & (DDIM - 1);
    size_t base = ((size_t)b * TLEN + (size_t)chunk * CHLEN) * DDIM + d;
    float la = -log1pf(expf(-Lam[d]));
    float h = 0.0f, P = 1.0f;
    for (int t = 0; t < CHLEN; t++) {
        size_t a_ = base + (size_t)t * DDIM;
        float r  = rt[a_];
        float iv = it[a_];
        float xv = rg[a_];
        float a = expf(la * sigmoidf_(r) * 0.125f);
        float g = sqrtf(fmaxf(1.0f - a * a, 0.0f)) * sigmoidf_(iv) * xv;
        h = fmaf(a, h, g);
        P *= a;
        hl[a_] = h;
    }
    Acar[i] = P;
    Hcar[i] = h;
}

__global__ void scan2_kernel(const float* __restrict__ Acar, const float* __restrict__ Hcar,
                             float* __restrict__ carry) {
    int chain = blockIdx.x * 256 + threadIdx.x;   // 0..4095
    float h = 0.0f;
    #pragma unroll
    for (int c = 0; c < CHUNKS; c++) {
        int idx = c * NCHAIN + chain;
        carry[idx] = h;
        h = fmaf(Acar[idx], h, Hcar[idx]);
    }
}

__global__ void scan3_kernel(const float* __restrict__ rt, const float* __restrict__ hl,
                             const float* __restrict__ carry, const float* __restrict__ lin,
                             const float* __restrict__ Lam,
                             __nv_bfloat16* __restrict__ Sh, __nv_bfloat16* __restrict__ Sl) {
    int i = blockIdx.x * 256 + threadIdx.x;
    int chain = i & (NCHAIN - 1);
    int chunk = i >> 12;
    int b = chain >> 10, d = chain & (DDIM - 1);
    size_t base = ((size_t)b * TLEN + (size_t)chunk * CHLEN) * DDIM + d;
    float la = -log1pf(expf(-Lam[d]));
    float cin = carry[i];
    float P = 1.0f;
    for (int t = 0; t < CHLEN; t++) {
        size_t a_ = base + (size_t)t * DDIM;
        float r = rt[a_];
        float a = expf(la * sigmoidf_(r) * 0.125f);
        P *= a;
        float h = fmaf(P, cin, hl[a_]);
        float l = lin[a_];
        float o = gelu_exact(l) * h;
        __nv_bfloat16 bh = __float2bfloat16_rn(o);
        __nv_bfloat16 bl = __float2bfloat16_rn(o - __bfloat162float(bh));
        Sh[a_] = bh;
        Sl[a_] = bl;
    }
}

// ---------------- gelu(sigmoid(t1)) * t2 -> bf16 split ---------------------
__global__ void comb_split_kernel(const float* __restrict__ t1,
                                  const float* __restrict__ t2,
                                  __nv_bfloat16* __restrict__ Sh,
                                  __nv_bfloat16* __restrict__ Sl) {
    int i = blockIdx.x * blockDim.x + threadIdx.x;
    if (i >= MROWS * DDIM / 4) return;
    float4 a = ((const float4*)t1)[i];
    float4 b = ((const float4*)t2)[i];
    float o0 = gelu_exact(sigmoidf_(a.x)) * b.x;
    float o1 = gelu_exact(sigmoidf_(a.y)) * b.y;
    float o2 = gelu_exact(sigmoidf_(a.z)) * b.z;
    float o3 = gelu_exact(sigmoidf_(a.w)) * b.w;
    __nv_bfloat162 h01, l01, h23, l23;
    split2(o0, o1, h01, l01);
    split2(o2, o3, h23, l23);
    ((__nv_bfloat162*)Sh)[2 * i]     = h01;
    ((__nv_bfloat162*)Sh)[2 * i + 1] = h23;
    ((__nv_bfloat162*)Sl)[2 * i]     = l01;
    ((__nv_bfloat162*)Sl)[2 * i + 1] = l23;
}

// ---------------- launch ---------------------------------------------------
extern "C" void kernel_launch(void* const* d_in, const int* in_sizes, int n_in,
                              void* d_out, int out_size) {
    const float* x      = (const float*)d_in[0];
    const float* g1     = (const float*)d_in[1];
    const float* g2     = (const float*)d_in[2];
    const float* W_lin  = (const float*)d_in[3];
    const float* b_lin  = (const float*)d_in[4];
    const float* W_conv = (const float*)d_in[5];
    const float* b_conv = (const float*)d_in[6];
    const float* W_lin2 = (const float*)d_in[7];
    const float* b_lin2 = (const float*)d_in[8];
    const float* Wa     = (const float*)d_in[9];
    const float* ba     = (const float*)d_in[10];
    const float* Wx     = (const float*)d_in[11];
    const float* bx     = (const float*)d_in[12];
    const float* Lam    = (const float*)d_in[13];
    const float* W1     = (const float*)d_in[14];
    const float* b1     = (const float*)d_in[15];
    const float* W2     = (const float*)d_in[16];
    const float* b2     = (const float*)d_in[17];
    const float* W3     = (const float*)d_in[18];
    const float* b3     = (const float*)d_in[19];
    float* out = (float*)d_out;

    float *lin, *rg, *rt, *it, *res, *hl, *Acar, *Hcar, *carry;
    __nv_bfloat16 *A0h, *A0l, *A1h, *A1l, *Wh, *Wl;
    __half *Af, *Wfh, *Wfl;
    cudaGetSymbolAddress((void**)&lin, g_lin);
    cudaGetSymbolAddress((void**)&rg,  g_rg);
    cudaGetSymbolAddress((void**)&rt,  g_rt);
    cudaGetSymbolAddress((void**)&it,  g_it);
    cudaGetSymbolAddress((void**)&res, g_res);
    cudaGetSymbolAddress((void**)&hl,  g_hl);
    cudaGetSymbolAddress((void**)&Acar, g_Acar);
    cudaGetSymbolAddress((void**)&Hcar, g_Hcar);
    cudaGetSymbolAddress((void**)&carry, g_carry);
    cudaGetSymbolAddress((void**)&A0h, g_A0h);
    cudaGetSymbolAddress((void**)&A0l, g_A0l);
    cudaGetSymbolAddress((void**)&A1h, g_A1h);
    cudaGetSymbolAddress((void**)&A1l, g_A1l);
    cudaGetSymbolAddress((void**)&Af,  g_Af);
    cudaGetSymbolAddress((void**)&Wh,  g_Wh);
    cudaGetSymbolAddress((void**)&Wl,  g_Wl);
    cudaGetSymbolAddress((void**)&Wfh, g_Wfh);
    cudaGetSymbolAddress((void**)&Wfl, g_Wfl);

    const int GEMM_SMEM  = 2 * STAGE_BYTES + 1024;   // 99328
    const int FGEMM_SMEM = 2 * F_STAGE + 1024;       // 66560
    cudaFuncSetAttribute(mma_gemm_kernel,
                         cudaFuncAttributeMaxDynamicSharedMemorySize, GEMM_SMEM);
    cudaFuncSetAttribute(mma_gemm_f16_kernel,
                         cudaFuncAttributeMaxDynamicSharedMemorySize, FGEMM_SMEM);

    dim3 gg1(DDIM / 64, MROWS / 128);        // (16, 128)  N=1024
    dim3 gg2(2 * DDIM / 64, MROWS / 128);    // (32, 128)  N=2048
    int ewBlocks  = (MROWS * DDIM / 4 + 255) / 256;
    int wBlocks   = (DDIM * DDIM / 4 + 255) / 256;
    int scBlocks  = (NCHAIN * CHUNKS) / 256;   // 512
    const int WN = DDIM * DDIM;

    #define SPLIT_W1(srcp) split_kernel<<<wBlocks, 256>>>(srcp, Wh, Wl, WN / 4)
    #define SPLIT_WF1(srcp) split_f16_kernel<<<wBlocks, 256>>>(srcp, Wfh, Wfl, WN / 4)
    #define SPLIT_WF2(srcp) split_f16_kernel<<<wBlocks, 256>>>(srcp, Wfh + WN, Wfl + WN, WN / 4)
    #define GEMM1(inH, inL, biasp, addq, outp, da, sh, sl, sf) \
        mma_gemm_kernel<<<gg1, 256, GEMM_SMEM>>>(inH, inL, Wh, Wl, biasp, addq, outp, da, sh, sl, sf)
    #define FGEMM2(inF, biaspA, outA, biaspB, outB) \
        mma_gemm_f16_kernel<<<gg2, 256, FGEMM_SMEM>>>(inF, Wfh, Wfl, biaspA, outA, biaspB, outB)

    // 1) A1 = bf16-split(rmsnorm(x, g1))
    rmsnorm_split_kernel<<<MROWS, 256>>>(x, g1, A1h, A1l, (__half*)nullptr);
    // 2) lin = xn @ W_lin^T + b_lin ; A0 = bf16-split(lin)
    SPLIT_W1(W_lin); GEMM1(A1h, A1l, b_lin, x, lin, 0, A0h, A0l, (__half*)nullptr);
    // 3) rg = lin @ W_conv^T + b_conv ; Af = fp16(rg)
    SPLIT_W1(W_conv); GEMM1(A0h, A0l, b_conv, x, rg, 0,
                            (__nv_bfloat16*)nullptr, (__nv_bfloat16*)nullptr, Af);
    // 4) merged fp16 2-term: rt = rg @ Wa^T + ba ; it = rg @ Wx^T + bx
    SPLIT_WF1(Wa); SPLIT_WF2(Wx);
    FGEMM2(Af, ba, rt, bx, it);
    // 5-7) chunked scan with fused gateprep + fused gelu(lin)*h + split
    scan1_kernel<<<scBlocks, 256>>>(rt, it, rg, Lam, hl, Acar, Hcar);
    scan2_kernel<<<NCHAIN / 256, 256>>>(Acar, Hcar, carry);
    scan3_kernel<<<scBlocks, 256>>>(rt, hl, carry, lin, Lam, A1h, A1l);
    // 8) res = (gelu(lin)*h) @ W_lin2^T + b_lin2 + x
    SPLIT_W1(W_lin2); GEMM1(A1h, A1l, b_lin2, x, res, 1,
                            (__nv_bfloat16*)nullptr, (__nv_bfloat16*)nullptr, (__half*)nullptr);
    // 9) A0 = bf16-split(rmsnorm(res, g2)) ; Af = fp16(xm)
    rmsnorm_split_kernel<<<MROWS, 256>>>(res, g2, (__nv_bfloat16*)nullptr,
                                         (__nv_bfloat16*)nullptr, Af);
    // 10) merged fp16 2-term: rt = xm @ W1^T + b1 ; it = xm @ W2^T + b2
    SPLIT_WF1(W1); SPLIT_WF2(W2);
    FGEMM2(Af, b1, rt, b2, it);
    // 11) A1 = bf16-split(gelu(sigmoid(rt)) * it)
    comb_split_kernel<<<ewBlocks, 256>>>(rt, it, A1h, A1l);
    // 12) out = combined @ W3^T + b3 + res
    SPLIT_W1(W3); GEMM1(A1h, A1l, b3, res, out, 1,
                        (__nv_bfloat16*)nullptr, (__nv_bfloat16*)nullptr, (__half*)nullptr);

    (void)in_sizes; (void)n_in; (void)out_size;
}

// round 9
// speedup vs baseline: 1.5132x; 1.2142x over previous
#include <cuda_runtime.h>
#include <cuda_fp16.h>
#include <math.h>
#include <cstdint>

// Problem dims
#define MROWS 16384   // B*T = 4*4096
#define DDIM  1024
#define TLEN  4096
#define CHUNKS 32
#define CHLEN  (TLEN / CHUNKS)   // 128
#define NCHAIN 4096              // B * D

// ---------------- scratch (device globals; no allocation allowed) ----------
__device__ float g_lin[MROWS * DDIM];
__device__ float g_rg [MROWS * DDIM];
__device__ float g_rt [MROWS * DDIM];
__device__ float g_it [MROWS * DDIM];
__device__ float g_res[MROWS * DDIM];
__device__ float g_hl [MROWS * DDIM];
__device__ __half g_Af [MROWS * DDIM];
__device__ __half g_Af2[MROWS * DDIM];
__device__ __half g_Wfh[2 * DDIM * DDIM];
__device__ __half g_Wfl[2 * DDIM * DDIM];
__device__ float g_Acar[NCHAIN * CHUNKS];
__device__ float g_Hcar[NCHAIN * CHUNKS];
__device__ float g_carry[NCHAIN * CHUNKS];

// ---------------- base-ISA tensor helpers ----------------------------------
__device__ __forceinline__ uint32_t smem_to_u32(const void* p) {
    uint32_t a;
    asm("{ .reg .u64 t; cvta.to.shared.u64 t, %1; cvt.u32.u64 %0, t; }"
        : "=r"(a) : "l"(p));
    return a;
}
__device__ __forceinline__ void cpasync16(uint32_t dst, const void* src) {
    asm volatile("cp.async.cg.shared.global [%0], [%1], 16;"
                 :: "r"(dst), "l"(src) : "memory");
}
#define CP_COMMIT() asm volatile("cp.async.commit_group;" ::: "memory")
#define CP_WAIT(n)  asm volatile("cp.async.wait_group %0;" :: "n"(n) : "memory")

__device__ __forceinline__ void ldsm4(uint32_t addr, uint32_t* r) {
    asm volatile("ldmatrix.sync.aligned.m8n8.x4.shared.b16 {%0,%1,%2,%3}, [%4];"
                 : "=r"(r[0]), "=r"(r[1]), "=r"(r[2]), "=r"(r[3]) : "r"(addr));
}
__device__ __forceinline__ void mma16816h(float* c, const uint32_t* a, const uint32_t* b) {
    asm volatile(
        "mma.sync.aligned.m16n8k16.row.col.f32.f16.f16.f32 "
        "{%0,%1,%2,%3}, {%4,%5,%6,%7}, {%8,%9}, {%0,%1,%2,%3};"
        : "+f"(c[0]), "+f"(c[1]), "+f"(c[2]), "+f"(c[3])
        : "r"(a[0]), "r"(a[1]), "r"(a[2]), "r"(a[3]), "r"(b[0]), "r"(b[1]));
}

// ---------------- math helpers ---------------------------------------------
__device__ __forceinline__ float gelu_exact(float x) {
    return 0.5f * x * (1.0f + erff(x * 0.70710678118654752440f));
}
__device__ __forceinline__ float sigmoidf_(float x) {
    return 1.0f / (1.0f + expf(-x));
}
__device__ __forceinline__ void split2h(float a, float b,
                                        __half2& h, __half2& l) {
    h = __floats2half2_rn(a, b);
    l = __floats2half2_rn(a - __low2float(h), b - __high2float(h));
}

// ---------------- fp32 -> (hi, lo) fp16 split (weights) --------------------
__global__ void split_f16_kernel(const float* __restrict__ src,
                                 __half* __restrict__ hi,
                                 __half* __restrict__ lo, int n4) {
    int i = blockIdx.x * 256 + threadIdx.x;
    if (i >= n4) return;
    float4 v = ((const float4*)src)[i];
    __half2 h01, l01, h23, l23;
    split2h(v.x, v.y, h01, l01);
    split2h(v.z, v.w, h23, l23);
    ((__half2*)hi)[2 * i]     = h01;
    ((__half2*)hi)[2 * i + 1] = h23;
    ((__half2*)lo)[2 * i]     = l01;
    ((__half2*)lo)[2 * i + 1] = l23;
}

// ---------------- fp16 2-term mma.sync GEMM --------------------------------
// C[M,N] = Af[M,K] @ (Wfh+Wfl)[N,K]^T + bias (+ add), fp32 accumulate.
// CTA tile 128x64, K-chunk 64, 2-stage, 256 threads, 2 CTAs/SM.
// N = 1024 (single: bias/addp/C/Sf) or 2048 (double: cols>=1024 -> bias2/C2).
#define F_TILE_A 16384               // 128 x 64 fp16
#define F_TILE_B 8192                // 64 x 64 fp16
#define F_STAGE  32768               // Af, Bh, Bl
#define NCHUNK (DDIM / 64)           // 16

__device__ __forceinline__ uint32_t swaddr(uint32_t tile, uint32_t row, uint32_t kb) {
    uint32_t off = row * 128u + kb;
    return tile + (off ^ ((off >> 3) & 0x70u));
}

__global__ void __launch_bounds__(256, 2)
fgemm_kernel(const __half* __restrict__ Af,
             const __half* __restrict__ Bh, const __half* __restrict__ Bl,
             const float* __restrict__ bias, const float* __restrict__ addp,
             float* __restrict__ C, int doAdd,
             __half* __restrict__ Sf,
             const float* __restrict__ bias2, float* __restrict__ C2) {
    extern __shared__ __align__(1024) char smem_raw[];
    uint32_t smem0 = smem_to_u32(smem_raw);
    uint32_t tbase = (smem0 + 1023u) & ~1023u;

    int tid = threadIdx.x;
    int wid = tid >> 5;
    int lane = tid & 31;
    int m0 = blockIdx.y * 128;
    int n0 = blockIdx.x * 64;

    // ---- producer mapping: 8 x 16B vecs per thread per stage ----
    int row_base = tid >> 3;
    int col = tid & 7;
    const char* srcb[8];
    uint32_t stsoff[8];
    {
        const char* aB = (const char*)(Af + (size_t)m0 * DDIM);
        const char* bB[2] = { (const char*)(Bh + (size_t)n0 * DDIM),
                              (const char*)(Bl + (size_t)n0 * DDIM) };
        #pragma unroll
        for (int i = 0; i < 4; i++) {
            uint32_t rr = (uint32_t)row_base + 32u * i;
            srcb[i] = aB + (size_t)rr * 2048 + col * 16;
            uint32_t off = rr * 128u + (uint32_t)col * 16u;
            stsoff[i] = off ^ ((off >> 3) & 0x70u);
        }
        #pragma unroll
        for (int i = 4; i < 8; i++) {
            uint32_t rr = (uint32_t)row_base + 32u * ((i - 4) & 1);
            srcb[i] = bB[(i - 4) >> 1] + (size_t)rr * 2048 + col * 16;
            uint32_t off = rr * 128u + (uint32_t)col * 16u;
            stsoff[i] = F_TILE_A + (uint32_t)((i - 4) >> 1) * F_TILE_B
                        + (off ^ ((off >> 3) & 0x70u));
        }
    }

    #define F_ISSUE(buf, chunk) do { \
        uint32_t db_ = tbase + (uint32_t)(buf) * F_STAGE; \
        _Pragma("unroll") \
        for (int i_ = 0; i_ < 8; i_++) \
            cpasync16(db_ + stsoff[i_], srcb[i_] + (size_t)(chunk) * 128); \
        CP_COMMIT(); \
    } while (0)

    // ---- consumer mapping: 8 warps, warp tile 32x32 (4 M x 2 N) ----
    int warp_m = wid & 3;
    int warp_n = wid >> 2;
    uint32_t ar  = (uint32_t)((lane & 7) + ((lane >> 3) & 1) * 8);
    uint32_t akb = (uint32_t)(((lane >> 4) & 1) * 16);
    uint32_t br  = (uint32_t)((lane & 7) + ((lane >> 4) & 1) * 8);
    uint32_t bkb = (uint32_t)(((lane >> 3) & 1) * 16);

    float acc[2][4][4];
    #pragma unroll
    for (int i = 0; i < 2; i++)
        #pragma unroll
        for (int j = 0; j < 4; j++)
            #pragma unroll
            for (int q = 0; q < 4; q++) acc[i][j][q] = 0.0f;

    F_ISSUE(0, 0);

    for (int c = 0; c < NCHUNK; c++) {
        CP_WAIT(0);
        __syncthreads();
        if (c + 1 < NCHUNK) F_ISSUE((c + 1) & 1, c + 1);

        uint32_t sb = tbase + (uint32_t)(c & 1) * F_STAGE;
        uint32_t tAf = sb;
        uint32_t tBh = sb + F_TILE_A;
        uint32_t tBl = sb + F_TILE_A + F_TILE_B;

        #pragma unroll
        for (int k16 = 0; k16 < 4; k16++) {
            uint32_t kb = (uint32_t)k16 * 32u;
            uint32_t af[2][4], bh[2][4], bl[2][4];
            #pragma unroll
            for (int mt = 0; mt < 2; mt++)
                ldsm4(swaddr(tAf, (uint32_t)(warp_m * 32 + mt * 16) + ar, kb + akb), af[mt]);
            #pragma unroll
            for (int p = 0; p < 2; p++)
                ldsm4(swaddr(tBh, (uint32_t)(warp_n * 32 + p * 16) + br, kb + bkb), bh[p]);
            #pragma unroll
            for (int mt = 0; mt < 2; mt++)
                #pragma unroll
                for (int p = 0; p < 2; p++) {
                    mma16816h(acc[mt][2 * p],     af[mt], &bh[p][0]);
                    mma16816h(acc[mt][2 * p + 1], af[mt], &bh[p][2]);
                }
            #pragma unroll
            for (int p = 0; p < 2; p++)
                ldsm4(swaddr(tBl, (uint32_t)(warp_n * 32 + p * 16) + br, kb + bkb), bl[p]);
            #pragma unroll
            for (int mt = 0; mt < 2; mt++)
                #pragma unroll
                for (int p = 0; p < 2; p++) {
                    mma16816h(acc[mt][2 * p],     af[mt], &bl[p][0]);
                    mma16816h(acc[mt][2 * p + 1], af[mt], &bl[p][2]);
                }
        }
    }

    // ---- epilogue ----
    float* Co = C;
    const float* bp = bias;
    if (n0 >= 1024) { Co = C2; bp = bias2; }
    int nbase = n0 & 1023;
    int lm = lane >> 2;
    int lc = (lane & 3) * 2;
    int cm = m0 + warp_m * 32;
    int cn = nbase + warp_n * 32;
    #pragma unroll
    for (int mt = 0; mt < 2; mt++) {
        #pragma unroll
        for (int nt = 0; nt < 4; nt++) {
            int r0 = cm + mt * 16 + lm;
            int cc = cn + nt * 8 + lc;
            float2 bv = *(const float2*)&bp[cc];
            float* a = acc[mt][nt];
            float2 o0 = make_float2(a[0] + bv.x, a[1] + bv.y);
            float2 o1 = make_float2(a[2] + bv.x, a[3] + bv.y);
            size_t off0 = (size_t)r0 * DDIM + cc;
            size_t off1 = (size_t)(r0 + 8) * DDIM + cc;
            if (doAdd) {
                float2 q0 = *(const float2*)(addp + off0);
                float2 q1 = *(const float2*)(addp + off1);
                o0.x += q0.x; o0.y += q0.y;
                o1.x += q1.x; o1.y += q1.y;
            }
            *(float2*)(Co + off0) = o0;
            *(float2*)(Co + off1) = o1;
            if (Sf) {
                *(__half2*)(Sf + off0) = __floats2half2_rn(o0.x, o0.y);
                *(__half2*)(Sf + off1) = __floats2half2_rn(o1.x, o1.y);
            }
        }
    }
}

// ---------------- rmsnorm -> fp16 ------------------------------------------
__global__ void rmsnorm_f16_kernel(const float* __restrict__ x,
                                   const float* __restrict__ gw,
                                   __half* __restrict__ Sf) {
    int row = blockIdx.x;
    const float4* xr = (const float4*)(x + (size_t)row * DDIM);
    float4 v = xr[threadIdx.x];
    float ss = v.x * v.x + v.y * v.y + v.z * v.z + v.w * v.w;
    #pragma unroll
    for (int o = 16; o > 0; o >>= 1) ss += __shfl_xor_sync(0xffffffffu, ss, o);
    __shared__ float sred[8];
    if ((threadIdx.x & 31) == 0) sred[threadIdx.x >> 5] = ss;
    __syncthreads();
    float total = 0.0f;
    #pragma unroll
    for (int i = 0; i < 8; i++) total += sred[i];
    float n = fmaxf(sqrtf(total), 1e-12f);
    float s = 32.0f / n;
    float4 g = ((const float4*)gw)[threadIdx.x];
    float o0 = v.x * s * g.x, o1 = v.y * s * g.y;
    float o2 = v.z * s * g.z, o3 = v.w * s * g.w;
    size_t base2 = (size_t)row * (DDIM / 2) + threadIdx.x * 2;
    ((__half2*)Sf)[base2]     = __floats2half2_rn(o0, o1);
    ((__half2*)Sf)[base2 + 1] = __floats2half2_rn(o2, o3);
}

// ---------------- chunked RG-LRU scan --------------------------------------
__global__ void scan1_kernel(const float* __restrict__ rt, const float* __restrict__ it,
                             const float* __restrict__ rg, const float* __restrict__ Lam,
                             float* __restrict__ hl,
                             float* __restrict__ Acar, float* __restrict__ Hcar) {
    int i = blockIdx.x * 256 + threadIdx.x;     // 0 .. 131071
    int chain = i & (NCHAIN - 1);
    int chunk = i >> 12;
    int b = chain >> 10, d = chain & (DDIM - 1);
    size_t base = ((size_t)b * TLEN + (size_t)chunk * CHLEN) * DDIM + d;
    float la = -log1pf(expf(-Lam[d]));
    float h = 0.0f, P = 1.0f;
    for (int t = 0; t < CHLEN; t++) {
        size_t a_ = base + (size_t)t * DDIM;
        float r  = rt[a_];
        float iv = it[a_];
        float xv = rg[a_];
        float a = expf(la * sigmoidf_(r) * 0.125f);
        float g = sqrtf(fmaxf(1.0f - a * a, 0.0f)) * sigmoidf_(iv) * xv;
        h = fmaf(a, h, g);
        P *= a;
        hl[a_] = h;
    }
    Acar[i] = P;
    Hcar[i] = h;
}

__global__ void scan2_kernel(const float* __restrict__ Acar, const float* __restrict__ Hcar,
                             float* __restrict__ carry) {
    int chain = blockIdx.x * 256 + threadIdx.x;   // 0..4095
    float h = 0.0f;
    #pragma unroll
    for (int c = 0; c < CHUNKS; c++) {
        int idx = c * NCHAIN + chain;
        carry[idx] = h;
        h = fmaf(Acar[idx], h, Hcar[idx]);
    }
}

// pass 3: apply carry, fused gelu(lin)*h, write fp16
__global__ void scan3_kernel(const float* __restrict__ rt, const float* __restrict__ hl,
                             const float* __restrict__ carry, const float* __restrict__ lin,
                             const float* __restrict__ Lam,
                             __half* __restrict__ Sf) {
    int i = blockIdx.x * 256 + threadIdx.x;
    int chain = i & (NCHAIN - 1);
    int chunk = i >> 12;
    int b = chain >> 10, d = chain & (DDIM - 1);
    size_t base = ((size_t)b * TLEN + (size_t)chunk * CHLEN) * DDIM + d;
    float la = -log1pf(expf(-Lam[d]));
    float cin = carry[i];
    float P = 1.0f;
    for (int t = 0; t < CHLEN; t++) {
        size_t a_ = base + (size_t)t * DDIM;
        float r = rt[a_];
        float a = expf(la * sigmoidf_(r) * 0.125f);
        P *= a;
        float h = fmaf(P, cin, hl[a_]);
        float l = lin[a_];
        float o = gelu_exact(l) * h;
        Sf[a_] = __float2half_rn(o);
    }
}

// ---------------- gelu(sigmoid(t1)) * t2 -> fp16 ---------------------------
__global__ void comb_f16_kernel(const float* __restrict__ t1,
                                const float* __restrict__ t2,
                                __half* __restrict__ Sf) {
    int i = blockIdx.x * blockDim.x + threadIdx.x;
    if (i >= MROWS * DDIM / 4) return;
    float4 a = ((const float4*)t1)[i];
    float4 b = ((const float4*)t2)[i];
    float o0 = gelu_exact(sigmoidf_(a.x)) * b.x;
    float o1 = gelu_exact(sigmoidf_(a.y)) * b.y;
    float o2 = gelu_exact(sigmoidf_(a.z)) * b.z;
    float o3 = gelu_exact(sigmoidf_(a.w)) * b.w;
    ((__half2*)Sf)[2 * i]     = __floats2half2_rn(o0, o1);
    ((__half2*)Sf)[2 * i + 1] = __floats2half2_rn(o2, o3);
}

// ---------------- launch ---------------------------------------------------
extern "C" void kernel_launch(void* const* d_in, const int* in_sizes, int n_in,
                              void* d_out, int out_size) {
    const float* x      = (const float*)d_in[0];
    const float* g1     = (const float*)d_in[1];
    const float* g2     = (const float*)d_in[2];
    const float* W_lin  = (const float*)d_in[3];
    const float* b_lin  = (const float*)d_in[4];
    const float* W_conv = (const float*)d_in[5];
    const float* b_conv = (const float*)d_in[6];
    const float* W_lin2 = (const float*)d_in[7];
    const float* b_lin2 = (const float*)d_in[8];
    const float* Wa     = (const float*)d_in[9];
    const float* ba     = (const float*)d_in[10];
    const float* Wx     = (const float*)d_in[11];
    const float* bx     = (const float*)d_in[12];
    const float* Lam    = (const float*)d_in[13];
    const float* W1     = (const float*)d_in[14];
    const float* b1     = (const float*)d_in[15];
    const float* W2     = (const float*)d_in[16];
    const float* b2     = (const float*)d_in[17];
    const float* W3     = (const float*)d_in[18];
    const float* b3     = (const float*)d_in[19];
    float* out = (float*)d_out;

    float *lin, *rg, *rt, *it, *res, *hl, *Acar, *Hcar, *carry;
    __half *Af, *Af2, *Wfh, *Wfl;
    cudaGetSymbolAddress((void**)&lin, g_lin);
    cudaGetSymbolAddress((void**)&rg,  g_rg);
    cudaGetSymbolAddress((void**)&rt,  g_rt);
    cudaGetSymbolAddress((void**)&it,  g_it);
    cudaGetSymbolAddress((void**)&res, g_res);
    cudaGetSymbolAddress((void**)&hl,  g_hl);
    cudaGetSymbolAddress((void**)&Acar, g_Acar);
    cudaGetSymbolAddress((void**)&Hcar, g_Hcar);
    cudaGetSymbolAddress((void**)&carry, g_carry);
    cudaGetSymbolAddress((void**)&Af,  g_Af);
    cudaGetSymbolAddress((void**)&Af2, g_Af2);
    cudaGetSymbolAddress((void**)&Wfh, g_Wfh);
    cudaGetSymbolAddress((void**)&Wfl, g_Wfl);

    const int FGEMM_SMEM = 2 * F_STAGE + 1024;       // 66560
    cudaFuncSetAttribute(fgemm_kernel,
                         cudaFuncAttributeMaxDynamicSharedMemorySize, FGEMM_SMEM);

    dim3 gg1(DDIM / 64, MROWS / 128);        // (16, 128)  N=1024
    dim3 gg2(2 * DDIM / 64, MROWS / 128);    // (32, 128)  N=2048
    int ewBlocks  = (MROWS * DDIM / 4 + 255) / 256;
    int wBlocks   = (DDIM * DDIM / 4 + 255) / 256;
    int scBlocks  = (NCHAIN * CHUNKS) / 256;   // 512
    const int WN = DDIM * DDIM;

    #define SPLIT_WF1(srcp) split_f16_kernel<<<wBlocks, 256>>>(srcp, Wfh, Wfl, WN / 4)
    #define SPLIT_WF2(srcp) split_f16_kernel<<<wBlocks, 256>>>(srcp, Wfh + WN, Wfl + WN, WN / 4)
    #define FGEMM1(inF, biasp, addq, outp, da, sf) \
        fgemm_kernel<<<gg1, 256, FGEMM_SMEM>>>(inF, Wfh, Wfl, biasp, addq, outp, da, sf, \
                                               (const float*)nullptr, (float*)nullptr)
    #define FGEMM2(inF, biaspA, outA, biaspB, outB) \
        fgemm_kernel<<<gg2, 256, FGEMM_SMEM>>>(inF, Wfh, Wfl, biaspA, (const float*)nullptr, \
                                               outA, 0, (__half*)nullptr, biaspB, outB)

    // 1) Af = fp16(rmsnorm(x, g1))
    rmsnorm_f16_kernel<<<MROWS, 256>>>(x, g1, Af);
    // 2) lin = xn @ W_lin^T + b_lin ; Af2 = fp16(lin)
    SPLIT_WF1(W_lin); FGEMM1(Af, b_lin, (const float*)nullptr, lin, 0, Af2);
    // 3) rg = lin @ W_conv^T + b_conv ; Af = fp16(rg)
    SPLIT_WF1(W_conv); FGEMM1(Af2, b_conv, (const float*)nullptr, rg, 0, Af);
    // 4) merged: rt = rg @ Wa^T + ba ; it = rg @ Wx^T + bx
    SPLIT_WF1(Wa); SPLIT_WF2(Wx);
    FGEMM2(Af, ba, rt, bx, it);
    // 5-7) chunked scan with fused gateprep + fused gelu(lin)*h -> fp16
    scan1_kernel<<<scBlocks, 256>>>(rt, it, rg, Lam, hl, Acar, Hcar);
    scan2_kernel<<<NCHAIN / 256, 256>>>(Acar, Hcar, carry);
    scan3_kernel<<<scBlocks, 256>>>(rt, hl, carry, lin, Lam, Af2);
    // 8) res = (gelu(lin)*h) @ W_lin2^T + b_lin2 + x
    SPLIT_WF1(W_lin2); FGEMM1(Af2, b_lin2, x, res, 1, (__half*)nullptr);
    // 9) Af = fp16(rmsnorm(res, g2))
    rmsnorm_f16_kernel<<<MROWS, 256>>>(res, g2, Af);
    // 10) merged: rt = xm @ W1^T + b1 ; it = xm @ W2^T + b2
    SPLIT_WF1(W1); SPLIT_WF2(W2);
    FGEMM2(Af, b1, rt, b2, it);
    // 11) Af2 = fp16(gelu(sigmoid(rt)) * it)
    comb_f16_kernel<<<ewBlocks, 256>>>(rt, it, Af2);
    // 12) out = combined @ W3^T + b3 + res
    SPLIT_WF1(W3); FGEMM1(Af2, b3, res, out, 1, (__half*)nullptr);

    (void)in_sizes; (void)n_in; (void)out_size;
}

// round 10
// speedup vs baseline: 2.0929x; 1.3831x over previous
#include <cuda_runtime.h>
#include <cuda_fp16.h>
#include <math.h>
#include <cstdint>

// Problem dims
#define MROWS 16384   // B*T = 4*4096
#define DDIM  1024
#define TLEN  4096
#define CHUNKS 32
#define CHLEN  (TLEN / CHUNKS)   // 128
#define NCHAIN 4096              // B * D

// ---------------- scratch (device globals; no allocation allowed) ----------
__device__ float g_lin[MROWS * DDIM];
__device__ float g_rg [MROWS * DDIM];
__device__ float g_rt [MROWS * DDIM];
__device__ float g_it [MROWS * DDIM];
__device__ float g_res[MROWS * DDIM];
__device__ float g_hl [MROWS * DDIM];
__device__ __half g_Af [MROWS * DDIM];
__device__ __half g_Af2[MROWS * DDIM];
__device__ __half g_Wf [2 * DDIM * DDIM];
__device__ float g_Acar[NCHAIN * CHUNKS];
__device__ float g_Hcar[NCHAIN * CHUNKS];
__device__ float g_carry[NCHAIN * CHUNKS];

// ---------------- base-ISA tensor helpers ----------------------------------
__device__ __forceinline__ uint32_t smem_to_u32(const void* p) {
    uint32_t a;
    asm("{ .reg .u64 t; cvta.to.shared.u64 t, %1; cvt.u32.u64 %0, t; }"
        : "=r"(a) : "l"(p));
    return a;
}
__device__ __forceinline__ void cpasync16(uint32_t dst, const void* src) {
    asm volatile("cp.async.cg.shared.global [%0], [%1], 16;"
                 :: "r"(dst), "l"(src) : "memory");
}
#define CP_COMMIT() asm volatile("cp.async.commit_group;" ::: "memory")
#define CP_WAIT(n)  asm volatile("cp.async.wait_group %0;" :: "n"(n) : "memory")

__device__ __forceinline__ void ldsm4(uint32_t addr, uint32_t* r) {
    asm volatile("ldmatrix.sync.aligned.m8n8.x4.shared.b16 {%0,%1,%2,%3}, [%4];"
                 : "=r"(r[0]), "=r"(r[1]), "=r"(r[2]), "=r"(r[3]) : "r"(addr));
}
__device__ __forceinline__ void mma16816h(float* c, const uint32_t* a, const uint32_t* b) {
    asm volatile(
        "mma.sync.aligned.m16n8k16.row.col.f32.f16.f16.f32 "
        "{%0,%1,%2,%3}, {%4,%5,%6,%7}, {%8,%9}, {%0,%1,%2,%3};"
        : "+f"(c[0]), "+f"(c[1]), "+f"(c[2]), "+f"(c[3])
        : "r"(a[0]), "r"(a[1]), "r"(a[2]), "r"(a[3]), "r"(b[0]), "r"(b[1]));
}

// ---------------- math helpers ---------------------------------------------
__device__ __forceinline__ float gelu_exact(float x) {
    return 0.5f * x * (1.0f + erff(x * 0.70710678118654752440f));
}
__device__ __forceinline__ float sigmoidf_(float x) {
    return 1.0f / (1.0f + expf(-x));
}

// ---------------- fp32 -> fp16 convert (weights) ---------------------------
__global__ void conv_f16_kernel(const float* __restrict__ src,
                                __half* __restrict__ dst, int n4) {
    int i = blockIdx.x * 256 + threadIdx.x;
    if (i >= n4) return;
    float4 v = ((const float4*)src)[i];
    ((__half2*)dst)[2 * i]     = __floats2half2_rn(v.x, v.y);
    ((__half2*)dst)[2 * i + 1] = __floats2half2_rn(v.z, v.w);
}

// ---------------- fp16 1-term mma.sync GEMM --------------------------------
// C[M,N] = Af[M,K] @ Wf[N,K]^T + bias (+ add), fp32 accumulate.
// CTA tile 128x64, K-chunk 64, 2-stage, 256 threads, 2 CTAs/SM.
// N = 1024 (single: bias/addp/C/Sf) or 2048 (double: cols>=1024 -> bias2/C2).
#define F_TILE_A 16384               // 128 x 64 fp16
#define F_TILE_B 8192                // 64 x 64 fp16
#define F_STAGE  24576               // Af, Bf
#define NCHUNK (DDIM / 64)           // 16

__device__ __forceinline__ uint32_t swaddr(uint32_t tile, uint32_t row, uint32_t kb) {
    uint32_t off = row * 128u + kb;
    return tile + (off ^ ((off >> 3) & 0x70u));
}

__global__ void __launch_bounds__(256, 2)
fgemm_kernel(const __half* __restrict__ Af, const __half* __restrict__ Bf,
             const float* __restrict__ bias, const float* __restrict__ addp,
             float* __restrict__ C, int doAdd,
             __half* __restrict__ Sf,
             const float* __restrict__ bias2, float* __restrict__ C2) {
    extern __shared__ __align__(1024) char smem_raw[];
    uint32_t smem0 = smem_to_u32(smem_raw);
    uint32_t tbase = (smem0 + 1023u) & ~1023u;

    int tid = threadIdx.x;
    int wid = tid >> 5;
    int lane = tid & 31;
    int m0 = blockIdx.y * 128;
    int n0 = blockIdx.x * 64;

    // ---- producer mapping: 6 x 16B vecs per thread per stage ----
    int row_base = tid >> 3;
    int col = tid & 7;
    const char* srcb[6];
    uint32_t stsoff[6];
    {
        const char* aB = (const char*)(Af + (size_t)m0 * DDIM);
        const char* bB = (const char*)(Bf + (size_t)n0 * DDIM);
        #pragma unroll
        for (int i = 0; i < 4; i++) {
            uint32_t rr = (uint32_t)row_base + 32u * i;
            srcb[i] = aB + (size_t)rr * 2048 + col * 16;
            uint32_t off = rr * 128u + (uint32_t)col * 16u;
            stsoff[i] = off ^ ((off >> 3) & 0x70u);
        }
        #pragma unroll
        for (int i = 4; i < 6; i++) {
            uint32_t rr = (uint32_t)row_base + 32u * (i - 4);
            srcb[i] = bB + (size_t)rr * 2048 + col * 16;
            uint32_t off = rr * 128u + (uint32_t)col * 16u;
            stsoff[i] = F_TILE_A + (off ^ ((off >> 3) & 0x70u));
        }
    }

    #define F_ISSUE(buf, chunk) do { \
        uint32_t db_ = tbase + (uint32_t)(buf) * F_STAGE; \
        _Pragma("unroll") \
        for (int i_ = 0; i_ < 6; i_++) \
            cpasync16(db_ + stsoff[i_], srcb[i_] + (size_t)(chunk) * 128); \
        CP_COMMIT(); \
    } while (0)

    // ---- consumer mapping: 8 warps, warp tile 32x32 (4 M x 2 N) ----
    int warp_m = wid & 3;
    int warp_n = wid >> 2;
    uint32_t ar  = (uint32_t)((lane & 7) + ((lane >> 3) & 1) * 8);
    uint32_t akb = (uint32_t)(((lane >> 4) & 1) * 16);
    uint32_t br  = (uint32_t)((lane & 7) + ((lane >> 4) & 1) * 8);
    uint32_t bkb = (uint32_t)(((lane >> 3) & 1) * 16);

    float acc[2][4][4];
    #pragma unroll
    for (int i = 0; i < 2; i++)
        #pragma unroll
        for (int j = 0; j < 4; j++)
            #pragma unroll
            for (int q = 0; q < 4; q++) acc[i][j][q] = 0.0f;

    F_ISSUE(0, 0);

    for (int c = 0; c < NCHUNK; c++) {
        CP_WAIT(0);
        __syncthreads();
        if (c + 1 < NCHUNK) F_ISSUE((c + 1) & 1, c + 1);

        uint32_t sb = tbase + (uint32_t)(c & 1) * F_STAGE;
        uint32_t tAf = sb;
        uint32_t tBf = sb + F_TILE_A;

        #pragma unroll
        for (int k16 = 0; k16 < 4; k16++) {
            uint32_t kb = (uint32_t)k16 * 32u;
            uint32_t af[2][4], bf[2][4];
            #pragma unroll
            for (int mt = 0; mt < 2; mt++)
                ldsm4(swaddr(tAf, (uint32_t)(warp_m * 32 + mt * 16) + ar, kb + akb), af[mt]);
            #pragma unroll
            for (int p = 0; p < 2; p++)
                ldsm4(swaddr(tBf, (uint32_t)(warp_n * 32 + p * 16) + br, kb + bkb), bf[p]);
            #pragma unroll
            for (int mt = 0; mt < 2; mt++)
                #pragma unroll
                for (int p = 0; p < 2; p++) {
                    mma16816h(acc[mt][2 * p],     af[mt], &bf[p][0]);
                    mma16816h(acc[mt][2 * p + 1], af[mt], &bf[p][2]);
                }
        }
    }

    // ---- epilogue ----
    float* Co = C;
    const float* bp = bias;
    if (n0 >= 1024) { Co = C2; bp = bias2; }
    int nbase = n0 & 1023;
    int lm = lane >> 2;
    int lc = (lane & 3) * 2;
    int cm = m0 + warp_m * 32;
    int cn = nbase + warp_n * 32;
    #pragma unroll
    for (int mt = 0; mt < 2; mt++) {
        #pragma unroll
        for (int nt = 0; nt < 4; nt++) {
            int r0 = cm + mt * 16 + lm;
            int cc = cn + nt * 8 + lc;
            float2 bv = *(const float2*)&bp[cc];
            float* a = acc[mt][nt];
            float2 o0 = make_float2(a[0] + bv.x, a[1] + bv.y);
            float2 o1 = make_float2(a[2] + bv.x, a[3] + bv.y);
            size_t off0 = (size_t)r0 * DDIM + cc;
            size_t off1 = (size_t)(r0 + 8) * DDIM + cc;
            if (doAdd) {
                float2 q0 = *(const float2*)(addp + off0);
                float2 q1 = *(const float2*)(addp + off1);
                o0.x += q0.x; o0.y += q0.y;
                o1.x += q1.x; o1.y += q1.y;
            }
            *(float2*)(Co + off0) = o0;
            *(float2*)(Co + off1) = o1;
            if (Sf) {
                *(__half2*)(Sf + off0) = __floats2half2_rn(o0.x, o0.y);
                *(__half2*)(Sf + off1) = __floats2half2_rn(o1.x, o1.y);
            }
        }
    }
}

// ---------------- rmsnorm -> fp16 ------------------------------------------
__global__ void rmsnorm_f16_kernel(const float* __restrict__ x,
                                   const float* __restrict__ gw,
                                   __half* __restrict__ Sf) {
    int row = blockIdx.x;
    const float4* xr = (const float4*)(x + (size_t)row * DDIM);
    float4 v = xr[threadIdx.x];
    float ss = v.x * v.x + v.y * v.y + v.z * v.z + v.w * v.w;
    #pragma unroll
    for (int o = 16; o > 0; o >>= 1) ss += __shfl_xor_sync(0xffffffffu, ss, o);
    __shared__ float sred[8];
    if ((threadIdx.x & 31) == 0) sred[threadIdx.x >> 5] = ss;
    __syncthreads();
    float total = 0.0f;
    #pragma unroll
    for (int i = 0; i < 8; i++) total += sred[i];
    float n = fmaxf(sqrtf(total), 1e-12f);
    float s = 32.0f / n;
    float4 g = ((const float4*)gw)[threadIdx.x];
    float o0 = v.x * s * g.x, o1 = v.y * s * g.y;
    float o2 = v.z * s * g.z, o3 = v.w * s * g.w;
    size_t base2 = (size_t)row * (DDIM / 2) + threadIdx.x * 2;
    ((__half2*)Sf)[base2]     = __floats2half2_rn(o0, o1);
    ((__half2*)Sf)[base2 + 1] = __floats2half2_rn(o2, o3);
}

// ---------------- chunked RG-LRU scan --------------------------------------
__global__ void scan1_kernel(const float* __restrict__ rt, const float* __restrict__ it,
                             const float* __restrict__ rg, const float* __restrict__ Lam,
                             float* __restrict__ hl,
                             float* __restrict__ Acar, float* __restrict__ Hcar) {
    int i = blockIdx.x * 256 + threadIdx.x;     // 0 .. 131071
    int chain = i & (NCHAIN - 1);
    int chunk = i >> 12;
    int b = chain >> 10, d = chain & (DDIM - 1);
    size_t base = ((size_t)b * TLEN + (size_t)chunk * CHLEN) * DDIM + d;
    float la = -log1pf(expf(-Lam[d]));
    float h = 0.0f, P = 1.0f;
    for (int t = 0; t < CHLEN; t++) {
        size_t a_ = base + (size_t)t * DDIM;
        float r  = rt[a_];
        float iv = it[a_];
        float xv = rg[a_];
        float a = expf(la * sigmoidf_(r) * 0.125f);
        float g = sqrtf(fmaxf(1.0f - a * a, 0.0f)) * sigmoidf_(iv) * xv;
        h = fmaf(a, h, g);
        P *= a;
        hl[a_] = h;
    }
    Acar[i] = P;
    Hcar[i] = h;
}

__global__ void scan2_kernel(const float* __restrict__ Acar, const float* __restrict__ Hcar,
                             float* __restrict__ carry) {
    int chain = blockIdx.x * 256 + threadIdx.x;   // 0..4095
    float h = 0.0f;
    #pragma unroll
    for (int c = 0; c < CHUNKS; c++) {
        int idx = c * NCHAIN + chain;
        carry[idx] = h;
        h = fmaf(Acar[idx], h, Hcar[idx]);
    }
}

// pass 3: apply carry, fused gelu(lin)*h, write fp16
__global__ void scan3_kernel(const float* __restrict__ rt, const float* __restrict__ hl,
                             const float* __restrict__ carry, const float* __restrict__ lin,
                             const float* __restrict__ Lam,
                             __half* __restrict__ Sf) {
    int i = blockIdx.x * 256 + threadIdx.x;
    int chain = i & (NCHAIN - 1);
    int chunk = i >> 12;
    int b = chain >> 10, d = chain & (DDIM - 1);
    size_t base = ((size_t)b * TLEN + (size_t)chunk * CHLEN) * DDIM + d;
    float la = -log1pf(expf(-Lam[d]));
    float cin = carry[i];
    float P = 1.0f;
    for (int t = 0; t < CHLEN; t++) {
        size_t a_ = base + (size_t)t * DDIM;
        float r = rt[a_];
        float a = expf(la * sigmoidf_(r) * 0.125f);
        P *= a;
        float h = fmaf(P, cin, hl[a_]);
        float l = lin[a_];
        float o = gelu_exact(l) * h;
        Sf[a_] = __float2half_rn(o);
    }
}

// ---------------- gelu(sigmoid(t1)) * t2 -> fp16 ---------------------------
__global__ void comb_f16_kernel(const float* __restrict__ t1,
                                const float* __restrict__ t2,
                                __half* __restrict__ Sf) {
    int i = blockIdx.x * blockDim.x + threadIdx.x;
    if (i >= MROWS * DDIM / 4) return;
    float4 a = ((const float4*)t1)[i];
    float4 b = ((const float4*)t2)[i];
    float o0 = gelu_exact(sigmoidf_(a.x)) * b.x;
    float o1 = gelu_exact(sigmoidf_(a.y)) * b.y;
    float o2 = gelu_exact(sigmoidf_(a.z)) * b.z;
    float o3 = gelu_exact(sigmoidf_(a.w)) * b.w;
    ((__half2*)Sf)[2 * i]     = __floats2half2_rn(o0, o1);
    ((__half2*)Sf)[2 * i + 1] = __floats2half2_rn(o2, o3);
}

// ---------------- launch ---------------------------------------------------
extern "C" void kernel_launch(void* const* d_in, const int* in_sizes, int n_in,
                              void* d_out, int out_size) {
    const float* x      = (const float*)d_in[0];
    const float* g1     = (const float*)d_in[1];
    const float* g2     = (const float*)d_in[2];
    const float* W_lin  = (const float*)d_in[3];
    const float* b_lin  = (const float*)d_in[4];
    const float* W_conv = (const float*)d_in[5];
    const float* b_conv = (const float*)d_in[6];
    const float* W_lin2 = (const float*)d_in[7];
    const float* b_lin2 = (const float*)d_in[8];
    const float* Wa     = (const float*)d_in[9];
    const float* ba     = (const float*)d_in[10];
    const float* Wx     = (const float*)d_in[11];
    const float* bx     = (const float*)d_in[12];
    const float* Lam    = (const float*)d_in[13];
    const float* W1     = (const float*)d_in[14];
    const float* b1     = (const float*)d_in[15];
    const float* W2     = (const float*)d_in[16];
    const float* b2     = (const float*)d_in[17];
    const float* W3     = (const float*)d_in[18];
    const float* b3     = (const float*)d_in[19];
    float* out = (float*)d_out;

    float *lin, *rg, *rt, *it, *res, *hl, *Acar, *Hcar, *carry;
    __half *Af, *Af2, *Wf;
    cudaGetSymbolAddress((void**)&lin, g_lin);
    cudaGetSymbolAddress((void**)&rg,  g_rg);
    cudaGetSymbolAddress((void**)&rt,  g_rt);
    cudaGetSymbolAddress((void**)&it,  g_it);
    cudaGetSymbolAddress((void**)&res, g_res);
    cudaGetSymbolAddress((void**)&hl,  g_hl);
    cudaGetSymbolAddress((void**)&Acar, g_Acar);
    cudaGetSymbolAddress((void**)&Hcar, g_Hcar);
    cudaGetSymbolAddress((void**)&carry, g_carry);
    cudaGetSymbolAddress((void**)&Af,  g_Af);
    cudaGetSymbolAddress((void**)&Af2, g_Af2);
    cudaGetSymbolAddress((void**)&Wf,  g_Wf);

    const int FGEMM_SMEM = 2 * F_STAGE + 1024;       // 50176
    cudaFuncSetAttribute(fgemm_kernel,
                         cudaFuncAttributeMaxDynamicSharedMemorySize, FGEMM_SMEM);

    dim3 gg1(DDIM / 64, MROWS / 128);        // (16, 128)  N=1024
    dim3 gg2(2 * DDIM / 64, MROWS / 128);    // (32, 128)  N=2048
    int ewBlocks  = (MROWS * DDIM / 4 + 255) / 256;
    int wBlocks   = (DDIM * DDIM / 4 + 255) / 256;
    int scBlocks  = (NCHAIN * CHUNKS) / 256;   // 512
    const int WN = DDIM * DDIM;

    #define CONV_W1(srcp) conv_f16_kernel<<<wBlocks, 256>>>(srcp, Wf, WN / 4)
    #define CONV_W2(srcp) conv_f16_kernel<<<wBlocks, 256>>>(srcp, Wf + WN, WN / 4)
    #define FGEMM1(inF, biasp, addq, outp, da, sf) \
        fgemm_kernel<<<gg1, 256, FGEMM_SMEM>>>(inF, Wf, biasp, addq, outp, da, sf, \
                                               (const float*)nullptr, (float*)nullptr)
    #define FGEMM2(inF, biaspA, outA, biaspB, outB) \
        fgemm_kernel<<<gg2, 256, FGEMM_SMEM>>>(inF, Wf, biaspA, (const float*)nullptr, \
                                               outA, 0, (__half*)nullptr, biaspB, outB)

    // 1) Af = fp16(rmsnorm(x, g1))
    rmsnorm_f16_kernel<<<MROWS, 256>>>(x, g1, Af);
    // 2) lin = xn @ W_lin^T + b_lin ; Af2 = fp16(lin)
    CONV_W1(W_lin); FGEMM1(Af, b_lin, (const float*)nullptr, lin, 0, Af2);
    // 3) rg = lin @ W_conv^T + b_conv ; Af = fp16(rg)
    CONV_W1(W_conv); FGEMM1(Af2, b_conv, (const float*)nullptr, rg, 0, Af);
    // 4) merged: rt = rg @ Wa^T + ba ; it = rg @ Wx^T + bx
    CONV_W1(Wa); CONV_W2(Wx);
    FGEMM2(Af, ba, rt, bx, it);
    // 5-7) chunked scan with fused gateprep + fused gelu(lin)*h -> fp16
    scan1_kernel<<<scBlocks, 256>>>(rt, it, rg, Lam, hl, Acar, Hcar);
    scan2_kernel<<<NCHAIN / 256, 256>>>(Acar, Hcar, carry);
    scan3_kernel<<<scBlocks, 256>>>(rt, hl, carry, lin, Lam, Af2);
    // 8) res = (gelu(lin)*h) @ W_lin2^T + b_lin2 + x
    CONV_W1(W_lin2); FGEMM1(Af2, b_lin2, x, res, 1, (__half*)nullptr);
    // 9) Af = fp16(rmsnorm(res, g2))
    rmsnorm_f16_kernel<<<MROWS, 256>>>(res, g2, Af);
    // 10) merged: rt = xm @ W1^T + b1 ; it = xm @ W2^T + b2
    CONV_W1(W1); CONV_W2(W2);
    FGEMM2(Af, b1, rt, b2, it);
    // 11) Af2 = fp16(gelu(sigmoid(rt)) * it)
    comb_f16_kernel<<<ewBlocks, 256>>>(rt, it, Af2);
    // 12) out = combined @ W3^T + b3 + res
    CONV_W1(W3); FGEMM1(Af2, b3, res, out, 1, (__half*)nullptr);

    (void)in_sizes; (void)n_in; (void)out_size;
}

// round 11
// speedup vs baseline: 2.4406x; 1.1661x over previous
#include <cuda_runtime.h>
#include <cuda_fp16.h>
#include <math.h>
#include <cstdint>

// Problem dims
#define MROWS 16384   // B*T = 4*4096
#define DDIM  1024
#define TLEN  4096
#define CHUNKS 32
#define CHLEN  (TLEN / CHUNKS)   // 128
#define NCHAIN 4096              // B * D

// ---------------- scratch (device globals; no allocation allowed) ----------
__device__ float g_res[MROWS * DDIM];
__device__ float g_hl [MROWS * DDIM];
__device__ __half g_Af  [MROWS * DDIM];
__device__ __half g_Af2 [MROWS * DDIM];
__device__ __half g_rt16[MROWS * DDIM];
__device__ __half g_it16[MROWS * DDIM];
__device__ __half g_Wf [2 * DDIM * DDIM];
__device__ float g_Acar[NCHAIN * CHUNKS];
__device__ float g_Hcar[NCHAIN * CHUNKS];
__device__ float g_carry[NCHAIN * CHUNKS];

// ---------------- base-ISA tensor helpers ----------------------------------
__device__ __forceinline__ uint32_t smem_to_u32(const void* p) {
    uint32_t a;
    asm("{ .reg .u64 t; cvta.to.shared.u64 t, %1; cvt.u32.u64 %0, t; }"
        : "=r"(a) : "l"(p));
    return a;
}
__device__ __forceinline__ void cpasync16(uint32_t dst, const void* src) {
    asm volatile("cp.async.cg.shared.global [%0], [%1], 16;"
                 :: "r"(dst), "l"(src) : "memory");
}
#define CP_COMMIT() asm volatile("cp.async.commit_group;" ::: "memory")
#define CP_WAIT(n)  asm volatile("cp.async.wait_group %0;" :: "n"(n) : "memory")

__device__ __forceinline__ void ldsm4(uint32_t addr, uint32_t* r) {
    asm volatile("ldmatrix.sync.aligned.m8n8.x4.shared.b16 {%0,%1,%2,%3}, [%4];"
                 : "=r"(r[0]), "=r"(r[1]), "=r"(r[2]), "=r"(r[3]) : "r"(addr));
}
__device__ __forceinline__ void mma16816h(float* c, const uint32_t* a, const uint32_t* b) {
    asm volatile(
        "mma.sync.aligned.m16n8k16.row.col.f32.f16.f16.f32 "
        "{%0,%1,%2,%3}, {%4,%5,%6,%7}, {%8,%9}, {%0,%1,%2,%3};"
        : "+f"(c[0]), "+f"(c[1]), "+f"(c[2]), "+f"(c[3])
        : "r"(a[0]), "r"(a[1]), "r"(a[2]), "r"(a[3]), "r"(b[0]), "r"(b[1]));
}

// ---------------- math helpers ---------------------------------------------
__device__ __forceinline__ float gelu_exact(float x) {
    return 0.5f * x * (1.0f + erff(x * 0.70710678118654752440f));
}
__device__ __forceinline__ float sigmoidf_(float x) {
    return 1.0f / (1.0f + expf(-x));
}

// ---------------- fp32 -> fp16 convert (weights) ---------------------------
__global__ void conv_f16_kernel(const float* __restrict__ src,
                                __half* __restrict__ dst, int n4) {
    int i = blockIdx.x * 256 + threadIdx.x;
    if (i >= n4) return;
    float4 v = ((const float4*)src)[i];
    ((__half2*)dst)[2 * i]     = __floats2half2_rn(v.x, v.y);
    ((__half2*)dst)[2 * i + 1] = __floats2half2_rn(v.z, v.w);
}

// ---------------- fp16 1-term mma.sync GEMM, BN=128 ------------------------
// CTA tile 128x128, K-chunk 64, 2-stage, 256 threads, 2 CTAs/SM.
// Warp grid 4(M) x 2(N), warp tile 32x64.
// N = 1024 (single) or 2048 (double: cols>=1024 -> bias2/C2/Sf2).
// Outputs per half: fp32 C (nullable, +bias, optional addp) and/or fp16 Sf.
#define F_TILE_A 16384               // 128 x 64 fp16
#define F_TILE_B 16384               // 128 x 64 fp16
#define F_STAGE  32768
#define NCHUNK (DDIM / 64)           // 16

__device__ __forceinline__ uint32_t swaddr(uint32_t tile, uint32_t row, uint32_t kb) {
    uint32_t off = row * 128u + kb;
    return tile + (off ^ ((off >> 3) & 0x70u));
}

__global__ void __launch_bounds__(256, 2)
fgemm_kernel(const __half* __restrict__ Af, const __half* __restrict__ Bf,
             const float* __restrict__ bias, const float* __restrict__ addp,
             float* __restrict__ C, int doAdd,
             __half* __restrict__ Sf,
             const float* __restrict__ bias2, float* __restrict__ C2,
             __half* __restrict__ Sf2) {
    extern __shared__ __align__(1024) char smem_raw[];
    uint32_t smem0 = smem_to_u32(smem_raw);
    uint32_t tbase = (smem0 + 1023u) & ~1023u;

    int tid = threadIdx.x;
    int wid = tid >> 5;
    int lane = tid & 31;
    int m0 = blockIdx.y * 128;
    int n0 = blockIdx.x * 128;

    // ---- producer mapping: 8 x 16B vecs per thread per stage ----
    int row_base = tid >> 3;        // 0..31
    int col = tid & 7;
    const char* srcb[8];
    uint32_t stsoff[8];
    {
        const char* aB = (const char*)(Af + (size_t)m0 * DDIM);
        const char* bB = (const char*)(Bf + (size_t)n0 * DDIM);
        #pragma unroll
        for (int i = 0; i < 4; i++) {
            uint32_t rr = (uint32_t)row_base + 32u * i;
            srcb[i] = aB + (size_t)rr * 2048 + col * 16;
            uint32_t off = rr * 128u + (uint32_t)col * 16u;
            stsoff[i] = off ^ ((off >> 3) & 0x70u);
        }
        #pragma unroll
        for (int i = 4; i < 8; i++) {
            uint32_t rr = (uint32_t)row_base + 32u * (i - 4);
            srcb[i] = bB + (size_t)rr * 2048 + col * 16;
            uint32_t off = rr * 128u + (uint32_t)col * 16u;
            stsoff[i] = F_TILE_A + (off ^ ((off >> 3) & 0x70u));
        }
    }

    #define F_ISSUE(buf, chunk) do { \
        uint32_t db_ = tbase + (uint32_t)(buf) * F_STAGE; \
        _Pragma("unroll") \
        for (int i_ = 0; i_ < 8; i_++) \
            cpasync16(db_ + stsoff[i_], srcb[i_] + (size_t)(chunk) * 128); \
        CP_COMMIT(); \
    } while (0)

    // ---- consumer mapping: 8 warps, warp tile 32x64 (4 M x 2 N) ----
    int warp_m = wid & 3;
    int warp_n = wid >> 2;          // 0..1
    uint32_t ar  = (uint32_t)((lane & 7) + ((lane >> 3) & 1) * 8);
    uint32_t akb = (uint32_t)(((lane >> 4) & 1) * 16);
    uint32_t br  = (uint32_t)((lane & 7) + ((lane >> 4) & 1) * 8);
    uint32_t bkb = (uint32_t)(((lane >> 3) & 1) * 16);

    float acc[2][8][4];
    #pragma unroll
    for (int i = 0; i < 2; i++)
        #pragma unroll
        for (int j = 0; j < 8; j++)
            #pragma unroll
            for (int q = 0; q < 4; q++) acc[i][j][q] = 0.0f;

    F_ISSUE(0, 0);

    for (int c = 0; c < NCHUNK; c++) {
        CP_WAIT(0);
        __syncthreads();
        if (c + 1 < NCHUNK) F_ISSUE((c + 1) & 1, c + 1);

        uint32_t sb = tbase + (uint32_t)(c & 1) * F_STAGE;
        uint32_t tAf = sb;
        uint32_t tBf = sb + F_TILE_A;

        #pragma unroll
        for (int k16 = 0; k16 < 4; k16++) {
            uint32_t kb = (uint32_t)k16 * 32u;
            uint32_t af[2][4], bf[4][4];
            #pragma unroll
            for (int mt = 0; mt < 2; mt++)
                ldsm4(swaddr(tAf, (uint32_t)(warp_m * 32 + mt * 16) + ar, kb + akb), af[mt]);
            #pragma unroll
            for (int p = 0; p < 4; p++)
                ldsm4(swaddr(tBf, (uint32_t)(warp_n * 64 + p * 16) + br, kb + bkb), bf[p]);
            #pragma unroll
            for (int mt = 0; mt < 2; mt++)
                #pragma unroll
                for (int p = 0; p < 4; p++) {
                    mma16816h(acc[mt][2 * p],     af[mt], &bf[p][0]);
                    mma16816h(acc[mt][2 * p + 1], af[mt], &bf[p][2]);
                }
        }
    }

    // ---- epilogue ----
    float* Co = C;
    const float* bp = bias;
    __half* So = Sf;
    if (n0 >= 1024) { Co = C2; bp = bias2; So = Sf2; }
    int nbase = n0 & 1023;
    int lm = lane >> 2;
    int lc = (lane & 3) * 2;
    int cm = m0 + warp_m * 32;
    int cn = nbase + warp_n * 64;
    #pragma unroll
    for (int mt = 0; mt < 2; mt++) {
        #pragma unroll
        for (int nt = 0; nt < 8; nt++) {
            int r0 = cm + mt * 16 + lm;
            int cc = cn + nt * 8 + lc;
            float2 bv = *(const float2*)&bp[cc];
            float* a = acc[mt][nt];
            float2 o0 = make_float2(a[0] + bv.x, a[1] + bv.y);
            float2 o1 = make_float2(a[2] + bv.x, a[3] + bv.y);
            size_t off0 = (size_t)r0 * DDIM + cc;
            size_t off1 = (size_t)(r0 + 8) * DDIM + cc;
            if (doAdd) {
                float2 q0 = *(const float2*)(addp + off0);
                float2 q1 = *(const float2*)(addp + off1);
                o0.x += q0.x; o0.y += q0.y;
                o1.x += q1.x; o1.y += q1.y;
            }
            if (Co) {
                *(float2*)(Co + off0) = o0;
                *(float2*)(Co + off1) = o1;
            }
            if (So) {
                *(__half2*)(So + off0) = __floats2half2_rn(o0.x, o0.y);
                *(__half2*)(So + off1) = __floats2half2_rn(o1.x, o1.y);
            }
        }
    }
}

// ---------------- rmsnorm -> fp16 ------------------------------------------
__global__ void rmsnorm_f16_kernel(const float* __restrict__ x,
                                   const float* __restrict__ gw,
                                   __half* __restrict__ Sf) {
    int row = blockIdx.x;
    const float4* xr = (const float4*)(x + (size_t)row * DDIM);
    float4 v = xr[threadIdx.x];
    float ss = v.x * v.x + v.y * v.y + v.z * v.z + v.w * v.w;
    #pragma unroll
    for (int o = 16; o > 0; o >>= 1) ss += __shfl_xor_sync(0xffffffffu, ss, o);
    __shared__ float sred[8];
    if ((threadIdx.x & 31) == 0) sred[threadIdx.x >> 5] = ss;
    __syncthreads();
    float total = 0.0f;
    #pragma unroll
    for (int i = 0; i < 8; i++) total += sred[i];
    float n = fmaxf(sqrtf(total), 1e-12f);
    float s = 32.0f / n;
    float4 g = ((const float4*)gw)[threadIdx.x];
    float o0 = v.x * s * g.x, o1 = v.y * s * g.y;
    float o2 = v.z * s * g.z, o3 = v.w * s * g.w;
    size_t base2 = (size_t)row * (DDIM / 2) + threadIdx.x * 2;
    ((__half2*)Sf)[base2]     = __floats2half2_rn(o0, o1);
    ((__half2*)Sf)[base2 + 1] = __floats2half2_rn(o2, o3);
}

// ---------------- chunked RG-LRU scan (fp16 inputs) ------------------------
__global__ void scan1_kernel(const __half* __restrict__ rt, const __half* __restrict__ it,
                             const __half* __restrict__ rg, const float* __restrict__ Lam,
                             float* __restrict__ hl,
                             float* __restrict__ Acar, float* __restrict__ Hcar) {
    int i = blockIdx.x * 256 + threadIdx.x;     // 0 .. 131071
    int chain = i & (NCHAIN - 1);
    int chunk = i >> 12;
    int b = chain >> 10, d = chain & (DDIM - 1);
    size_t base = ((size_t)b * TLEN + (size_t)chunk * CHLEN) * DDIM + d;
    float la = -log1pf(expf(-Lam[d]));
    float h = 0.0f, P = 1.0f;
    for (int t = 0; t < CHLEN; t++) {
        size_t a_ = base + (size_t)t * DDIM;
        float r  = __half2float(rt[a_]);
        float iv = __half2float(it[a_]);
        float xv = __half2float(rg[a_]);
        float a = expf(la * sigmoidf_(r) * 0.125f);
        float g = sqrtf(fmaxf(1.0f - a * a, 0.0f)) * sigmoidf_(iv) * xv;
        h = fmaf(a, h, g);
        P *= a;
        hl[a_] = h;
    }
    Acar[i] = P;
    Hcar[i] = h;
}

__global__ void scan2_kernel(const float* __restrict__ Acar, const float* __restrict__ Hcar,
                             float* __restrict__ carry) {
    int chain = blockIdx.x * 256 + threadIdx.x;   // 0..4095
    float h = 0.0f;
    #pragma unroll
    for (int c = 0; c < CHUNKS; c++) {
        int idx = c * NCHAIN + chain;
        carry[idx] = h;
        h = fmaf(Acar[idx], h, Hcar[idx]);
    }
}

// pass 3: apply carry, fused gelu(lin)*h, fp16 in-place on lin buffer
__global__ void scan3_kernel(const __half* __restrict__ rt, const float* __restrict__ hl,
                             const float* __restrict__ carry,
                             const float* __restrict__ Lam,
                             __half* __restrict__ linSf) {
    int i = blockIdx.x * 256 + threadIdx.x;
    int chain = i & (NCHAIN - 1);
    int chunk = i >> 12;
    int b = chain >> 10, d = chain & (DDIM - 1);
    size_t base = ((size_t)b * TLEN + (size_t)chunk * CHLEN) * DDIM + d;
    float la = -log1pf(expf(-Lam[d]));
    float cin = carry[i];
    float P = 1.0f;
    for (int t = 0; t < CHLEN; t++) {
        size_t a_ = base + (size_t)t * DDIM;
        float r = __half2float(rt[a_]);
        float a = expf(la * sigmoidf_(r) * 0.125f);
        P *= a;
        float h = fmaf(P, cin, hl[a_]);
        float l = __half2float(linSf[a_]);
        float o = gelu_exact(l) * h;
        linSf[a_] = __float2half_rn(o);
    }
}

// ---------------- gelu(sigmoid(t1)) * t2 -> fp16 ---------------------------
__global__ void comb_f16_kernel(const __half* __restrict__ t1,
                                const __half* __restrict__ t2,
                                __half* __restrict__ Sf) {
    int i = blockIdx.x * blockDim.x + threadIdx.x;
    if (i >= MROWS * DDIM / 2) return;
    __half2 a2 = ((const __half2*)t1)[i];
    __half2 b2 = ((const __half2*)t2)[i];
    float a0 = __low2float(a2), a1 = __high2float(a2);
    float b0 = __low2float(b2), b1 = __high2float(b2);
    float o0 = gelu_exact(sigmoidf_(a0)) * b0;
    float o1 = gelu_exact(sigmoidf_(a1)) * b1;
    ((__half2*)Sf)[i] = __floats2half2_rn(o0, o1);
}

// ---------------- launch ---------------------------------------------------
extern "C" void kernel_launch(void* const* d_in, const int* in_sizes, int n_in,
                              void* d_out, int out_size) {
    const float* x      = (const float*)d_in[0];
    const float* g1     = (const float*)d_in[1];
    const float* g2     = (const float*)d_in[2];
    const float* W_lin  = (const float*)d_in[3];
    const float* b_lin  = (const float*)d_in[4];
    const float* W_conv = (const float*)d_in[5];
    const float* b_conv = (const float*)d_in[6];
    const float* W_lin2 = (const float*)d_in[7];
    const float* b_lin2 = (const float*)d_in[8];
    const float* Wa     = (const float*)d_in[9];
    const float* ba     = (const float*)d_in[10];
    const float* Wx     = (const float*)d_in[11];
    const float* bx     = (const float*)d_in[12];
    const float* Lam    = (const float*)d_in[13];
    const float* W1     = (const float*)d_in[14];
    const float* b1     = (const float*)d_in[15];
    const float* W2     = (const float*)d_in[16];
    const float* b2     = (const float*)d_in[17];
    const float* W3     = (const float*)d_in[18];
    const float* b3     = (const float*)d_in[19];
    float* out = (float*)d_out;

    float *res, *hl, *Acar, *Hcar, *carry;
    __half *Af, *Af2, *rt16, *it16, *Wf;
    cudaGetSymbolAddress((void**)&res, g_res);
    cudaGetSymbolAddress((void**)&hl,  g_hl);
    cudaGetSymbolAddress((void**)&Acar, g_Acar);
    cudaGetSymbolAddress((void**)&Hcar, g_Hcar);
    cudaGetSymbolAddress((void**)&carry, g_carry);
    cudaGetSymbolAddress((void**)&Af,   g_Af);
    cudaGetSymbolAddress((void**)&Af2,  g_Af2);
    cudaGetSymbolAddress((void**)&rt16, g_rt16);
    cudaGetSymbolAddress((void**)&it16, g_it16);
    cudaGetSymbolAddress((void**)&Wf,   g_Wf);

    const int FGEMM_SMEM = 2 * F_STAGE + 1024;       // 66560
    cudaFuncSetAttribute(fgemm_kernel,
                         cudaFuncAttributeMaxDynamicSharedMemorySize, FGEMM_SMEM);

    dim3 gg1(DDIM / 128, MROWS / 128);       // (8, 128)   N=1024
    dim3 gg2(2 * DDIM / 128, MROWS / 128);   // (16, 128)  N=2048
    int ewBlocks  = (MROWS * DDIM / 2 + 255) / 256;
    int wBlocks   = (DDIM * DDIM / 4 + 255) / 256;
    int scBlocks  = (NCHAIN * CHUNKS) / 256;   // 512
    const int WN = DDIM * DDIM;

    const float* FZ = (const float*)nullptr;
    float* FZo = (float*)nullptr;
    __half* HZ = (__half*)nullptr;

    #define CONV_W1(srcp) conv_f16_kernel<<<wBlocks, 256>>>(srcp, Wf, WN / 4)
    #define CONV_W2(srcp) conv_f16_kernel<<<wBlocks, 256>>>(srcp, Wf + WN, WN / 4)

    // 1) Af = fp16(rmsnorm(x, g1))
    rmsnorm_f16_kernel<<<MROWS, 256>>>(x, g1, Af);
    // 2) lin(fp16 Af2) = xn @ W_lin^T + b_lin
    CONV_W1(W_lin);
    fgemm_kernel<<<gg1, 256, FGEMM_SMEM>>>(Af, Wf, b_lin, FZ, FZo, 0, Af2, FZ, FZo, HZ);
    // 3) rg(fp16 Af) = lin @ W_conv^T + b_conv
    CONV_W1(W_conv);
    fgemm_kernel<<<gg1, 256, FGEMM_SMEM>>>(Af2, Wf, b_conv, FZ, FZo, 0, Af, FZ, FZo, HZ);
    // 4) merged: rt16 = rg @ Wa^T + ba ; it16 = rg @ Wx^T + bx
    CONV_W1(Wa); CONV_W2(Wx);
    fgemm_kernel<<<gg2, 256, FGEMM_SMEM>>>(Af, Wf, ba, FZ, FZo, 0, rt16, bx, FZo, it16);
    // 5-7) chunked scan: gateprep + local scan, aggregate scan, carry + gelu*h
    scan1_kernel<<<scBlocks, 256>>>(rt16, it16, Af, Lam, hl, Acar, Hcar);
    scan2_kernel<<<NCHAIN / 256, 256>>>(Acar, Hcar, carry);
    scan3_kernel<<<scBlocks, 256>>>(rt16, hl, carry, Lam, Af2);
    // 8) res = (gelu(lin)*h) @ W_lin2^T + b_lin2 + x
    CONV_W1(W_lin2);
    fgemm_kernel<<<gg1, 256, FGEMM_SMEM>>>(Af2, Wf, b_lin2, x, res, 1, HZ, FZ, FZo, HZ);
    // 9) Af = fp16(rmsnorm(res, g2))
    rmsnorm_f16_kernel<<<MROWS, 256>>>(res, g2, Af);
    // 10) merged: rt16 = xm @ W1^T + b1 ; it16 = xm @ W2^T + b2
    CONV_W1(W1); CONV_W2(W2);
    fgemm_kernel<<<gg2, 256, FGEMM_SMEM>>>(Af, Wf, b1, FZ, FZo, 0, rt16, b2, FZo, it16);
    // 11) Af2 = fp16(gelu(sigmoid(rt)) * it)
    comb_f16_kernel<<<ewBlocks, 256>>>(rt16, it16, Af2);
    // 12) out = combined @ W3^T + b3 + res
    CONV_W1(W3);
    fgemm_kernel<<<gg1, 256, FGEMM_SMEM>>>(Af2, Wf, b3, res, out, 1, HZ, FZ, FZo, HZ);

    (void)in_sizes; (void)n_in; (void)out_size;
}